// round 5
// baseline (speedup 1.0000x reference)
#include <cuda_runtime.h>

// B=4, T=2048, C=768, H=12, D=64, 3C=2304, BH=48

typedef unsigned long long ull;

__device__ float g_qkv  [4*2048*2304];   // [B,T,3C]
__device__ float g_kur  [48*2048*64];    // k @ Ur   [B*H,T,D]
__device__ float g_kun  [48*2048*64];    // k @ Un
__device__ float g_local[48*2048*64];    // attention out
__device__ float g_rnn  [48*2048*64];    // scan out
__device__ float g_alpha[4*2048*12];     // gate [B*T,H]
__device__ float g_y    [4*2048*768];    // mixed
__device__ int   g_win;

// ---- packed f32x2 helpers (sm_103a FFMA2 — ptxas never auto-emits) ---------
__device__ __forceinline__ ull ffma2(ull a, ull b, ull c) {
    ull d;
    asm("fma.rn.f32x2 %0, %1, %2, %3;" : "=l"(d) : "l"(a), "l"(b), "l"(c));
    return d;
}
__device__ __forceinline__ ull mul2(ull a, ull b) {
    ull d;
    asm("mul.rn.f32x2 %0, %1, %2;" : "=l"(d) : "l"(a), "l"(b));
    return d;
}
__device__ __forceinline__ ull pk2(float x, float y) {
    ull r;
    asm("mov.b64 %0, {%1, %2};" : "=l"(r) : "f"(x), "f"(y));
    return r;
}
__device__ __forceinline__ float2 up2(ull v) {
    float2 f;
    asm("mov.b64 {%0, %1}, %2;" : "=f"(f.x), "=f"(f.y) : "l"(v));
    return f;
}

// ---- window scalar normalization -------------------------------------------
__global__ void win_kernel(const void* wp) {
    int v = *(const int*)wp;
    if (v < 1 || v > 4096) {
        float f = *(const float*)wp;
        int vf = (int)f;
        if (vf >= 1 && vf <= 4096) v = vf; else v = 256;
    }
    g_win = v;
}

// ---- SGEMM + bias: 128x128x16, 256 thr, FFMA2 + double-buffered smem -------
__global__ __launch_bounds__(256) void sgemm_bias(
    const float* __restrict__ A, const float* __restrict__ Bm,
    const float* __restrict__ bias, float* __restrict__ C,
    int M, int N, int K)
{
    __shared__ float As[2][16][132];
    __shared__ float Bs[2][16][128];
    const int tid = threadIdx.x;
    const int bm = blockIdx.y * 128, bn = blockIdx.x * 128;
    const int tx = tid & 15, ty = tid >> 4;

    ull accP[8][4];
#pragma unroll
    for (int i = 0; i < 8; i++)
#pragma unroll
        for (int j = 0; j < 4; j++) accP[i][j] = 0ull;

    // load tile 0
    {
#pragma unroll
        for (int i = 0; i < 2; i++) {
            int s = i * 256 + tid;
            int r = s >> 2, kk = (s & 3) << 2;
            float4 a = *(const float4*)(A + (size_t)(bm + r) * K + kk);
            As[0][kk + 0][r] = a.x; As[0][kk + 1][r] = a.y;
            As[0][kk + 2][r] = a.z; As[0][kk + 3][r] = a.w;
        }
#pragma unroll
        for (int i = 0; i < 2; i++) {
            int s = i * 256 + tid;
            int r = s >> 5, cc = (s & 31) << 2;
            *(float4*)(&Bs[0][r][cc]) = *(const float4*)(Bm + (size_t)r * N + bn + cc);
        }
    }
    __syncthreads();

    int buf = 0;
    for (int k0 = 0; k0 < K; k0 += 16) {
        const bool has_next = (k0 + 16) < K;
        float4 apre[2], bpre[2];
        if (has_next) {
#pragma unroll
            for (int i = 0; i < 2; i++) {
                int s = i * 256 + tid;
                int r = s >> 2, kk = (s & 3) << 2;
                apre[i] = *(const float4*)(A + (size_t)(bm + r) * K + k0 + 16 + kk);
            }
#pragma unroll
            for (int i = 0; i < 2; i++) {
                int s = i * 256 + tid;
                int r = s >> 5, cc = (s & 31) << 2;
                bpre[i] = *(const float4*)(Bm + (size_t)(k0 + 16 + r) * N + bn + cc);
            }
        }
#pragma unroll
        for (int kk = 0; kk < 16; kk++) {
            float a[8];
            *(float4*)&a[0] = *(float4*)&As[buf][kk][ty * 4];
            *(float4*)&a[4] = *(float4*)&As[buf][kk][64 + ty * 4];
            ull b[4];
            {
                const ull* bp0 = (const ull*)&Bs[buf][kk][tx * 4];
                const ull* bp1 = (const ull*)&Bs[buf][kk][64 + tx * 4];
                b[0] = bp0[0]; b[1] = bp0[1];
                b[2] = bp1[0]; b[3] = bp1[1];
            }
#pragma unroll
            for (int i = 0; i < 8; i++) {
                ull ad = pk2(a[i], a[i]);
#pragma unroll
                for (int j = 0; j < 4; j++)
                    accP[i][j] = ffma2(ad, b[j], accP[i][j]);
            }
        }
        if (has_next) {
            int nb = buf ^ 1;
#pragma unroll
            for (int i = 0; i < 2; i++) {
                int s = i * 256 + tid;
                int r = s >> 2, kk = (s & 3) << 2;
                As[nb][kk + 0][r] = apre[i].x; As[nb][kk + 1][r] = apre[i].y;
                As[nb][kk + 2][r] = apre[i].z; As[nb][kk + 3][r] = apre[i].w;
            }
#pragma unroll
            for (int i = 0; i < 2; i++) {
                int s = i * 256 + tid;
                int r = s >> 5, cc = (s & 31) << 2;
                *(float4*)(&Bs[nb][r][cc]) = bpre[i];
            }
        }
        __syncthreads();
        buf ^= 1;
    }

#pragma unroll
    for (int ih = 0; ih < 2; ih++)
#pragma unroll
        for (int i = 0; i < 4; i++) {
            int r = bm + ih * 64 + ty * 4 + i;
#pragma unroll
            for (int jh = 0; jh < 2; jh++) {
                int cc = bn + jh * 64 + tx * 4;
                float4 bv = *(const float4*)(bias + cc);
                float2 p0 = up2(accP[ih * 4 + i][jh * 2 + 0]);
                float2 p1 = up2(accP[ih * 4 + i][jh * 2 + 1]);
                float4 o;
                o.x = p0.x + bv.x; o.y = p0.y + bv.y;
                o.z = p1.x + bv.z; o.w = p1.y + bv.w;
                *(float4*)(C + (size_t)r * N + cc) = o;
            }
        }
}

// ---- kUr/kUn: per (b,h), 64-row time tiles ---------------------------------
__global__ __launch_bounds__(256) void ku_kernel(
    const float* __restrict__ Ur, const float* __restrict__ Un)
{
    __shared__ float ks[64][64];
    __shared__ float ur[64][64];
    __shared__ float un[64][64];
    const int t64 = blockIdx.x, bh = blockIdx.y;
    const int b = bh / 12, h = bh - b * 12;
    const int tid = threadIdx.x;
#pragma unroll
    for (int i = 0; i < 4; i++) {
        int s = i * 256 + tid;
        ((float4*)ur)[s] = ((const float4*)Ur)[s];
        ((float4*)un)[s] = ((const float4*)Un)[s];
    }
    const float* kb = g_qkv + ((size_t)(b * 2048 + t64 * 64)) * 2304 + 768 + h * 64;
#pragma unroll
    for (int q = 0; q < 4; q++) {
        int s = q * 256 + tid;
        int r = s >> 4, d0 = (s & 15) << 2;
        *(float4*)&ks[r][d0] = *(const float4*)(kb + (size_t)r * 2304 + d0);
    }
    __syncthreads();
    const int tx = tid & 15, ty = tid >> 4;
    ull ar[4][2], an[4][2];
#pragma unroll
    for (int i = 0; i < 4; i++)
#pragma unroll
        for (int j = 0; j < 2; j++) { ar[i][j] = 0ull; an[i][j] = 0ull; }

    for (int i0 = 0; i0 < 64; i0 += 4) {
        float krr[4][4];
#pragma unroll
        for (int rr = 0; rr < 4; rr++)
            *(float4*)&krr[rr][0] = *(const float4*)&ks[ty * 4 + rr][i0];
#pragma unroll
        for (int q = 0; q < 4; q++) {
            const ull* uR2 = (const ull*)&ur[i0 + q][tx * 4];
            const ull* uN2 = (const ull*)&un[i0 + q][tx * 4];
            ull uR0 = uR2[0], uR1 = uR2[1], uN0 = uN2[0], uN1 = uN2[1];
#pragma unroll
            for (int rr = 0; rr < 4; rr++) {
                ull kd = pk2(krr[rr][q], krr[rr][q]);
                ar[rr][0] = ffma2(kd, uR0, ar[rr][0]);
                ar[rr][1] = ffma2(kd, uR1, ar[rr][1]);
                an[rr][0] = ffma2(kd, uN0, an[rr][0]);
                an[rr][1] = ffma2(kd, uN1, an[rr][1]);
            }
        }
    }
    float* outR = g_kur + ((size_t)bh * 2048 + t64 * 64) * 64;
    float* outN = g_kun + ((size_t)bh * 2048 + t64 * 64) * 64;
#pragma unroll
    for (int rr = 0; rr < 4; rr++) {
        float2 r0 = up2(ar[rr][0]), r1 = up2(ar[rr][1]);
        float2 n0 = up2(an[rr][0]), n1 = up2(an[rr][1]);
        float4 oR = make_float4(r0.x, r0.y, r1.x, r1.y);
        float4 oN = make_float4(n0.x, n0.y, n1.x, n1.y);
        *(float4*)&outR[(size_t)(ty * 4 + rr) * 64 + tx * 4] = oR;
        *(float4*)&outN[(size_t)(ty * 4 + rr) * 64 + tx * 4] = oN;
    }
}

// ---- windowed flash attention, 64x64 tiles, FFMA2 mainloops ----------------
__global__ __launch_bounds__(256) void attn_kernel()
{
    extern __shared__ float sm[];
    float* qs = sm;                  // [d][r] stride 68
    float* ks = qs + 64 * 68;        // [d][j]
    float* vs = ks + 64 * 68;        // [j][d]
    float* ps = vs + 64 * 68;        // [j][r]
    const int qt = blockIdx.x, bh = blockIdx.y;
    const int b = bh / 12, h = bh - b * 12;
    const int tid = threadIdx.x;
    const int tx = tid & 15, ty = tid >> 4;
    const int win = g_win;

    const float* qbase = g_qkv + ((size_t)(b * 2048 + qt * 64)) * 2304 + h * 64;
#pragma unroll
    for (int q = 0; q < 4; q++) {
        int s = q * 256 + tid;
        int r = s >> 4, d0 = (s & 15) << 2;
        float4 v = *(const float4*)(qbase + (size_t)r * 2304 + d0);
        qs[(d0 + 0) * 68 + r] = v.x; qs[(d0 + 1) * 68 + r] = v.y;
        qs[(d0 + 2) * 68 + r] = v.z; qs[(d0 + 3) * 68 + r] = v.w;
    }
    ull opk[4][2];
    float m[4], l[4];
#pragma unroll
    for (int i = 0; i < 4; i++) {
        m[i] = -1e30f; l[i] = 0.f;
        opk[i][0] = 0ull; opk[i][1] = 0ull;
    }
    int ktmax = (qt * 64 + 63 + win - 1) >> 6;
    if (ktmax > 31) ktmax = 31;

    for (int kt = qt; kt <= ktmax; kt++) {
        __syncthreads();
        const float* kb = g_qkv + ((size_t)(b * 2048 + kt * 64)) * 2304 + 768 + h * 64;
        const float* vb = kb + 768;
#pragma unroll
        for (int q = 0; q < 4; q++) {
            int s = q * 256 + tid;
            int r = s >> 4, d0 = (s & 15) << 2;
            float4 kv = *(const float4*)(kb + (size_t)r * 2304 + d0);
            ks[(d0 + 0) * 68 + r] = kv.x; ks[(d0 + 1) * 68 + r] = kv.y;
            ks[(d0 + 2) * 68 + r] = kv.z; ks[(d0 + 3) * 68 + r] = kv.w;
            *(float4*)&vs[r * 68 + d0] = *(const float4*)(vb + (size_t)r * 2304 + d0);
        }
        __syncthreads();

        ull sp[4][2];
#pragma unroll
        for (int i = 0; i < 4; i++) { sp[i][0] = 0ull; sp[i][1] = 0ull; }
#pragma unroll 8
        for (int d = 0; d < 64; d++) {
            float4 qv = *(float4*)&qs[d * 68 + ty * 4];
            const ull* kp = (const ull*)&ks[d * 68 + tx * 4];
            ull k0 = kp[0], k1 = kp[1];
            ull q0 = pk2(qv.x, qv.x), q1 = pk2(qv.y, qv.y);
            ull q2 = pk2(qv.z, qv.z), q3 = pk2(qv.w, qv.w);
            sp[0][0] = ffma2(q0, k0, sp[0][0]); sp[0][1] = ffma2(q0, k1, sp[0][1]);
            sp[1][0] = ffma2(q1, k0, sp[1][0]); sp[1][1] = ffma2(q1, k1, sp[1][1]);
            sp[2][0] = ffma2(q2, k0, sp[2][0]); sp[2][1] = ffma2(q2, k1, sp[2][1]);
            sp[3][0] = ffma2(q3, k0, sp[3][0]); sp[3][1] = ffma2(q3, k1, sp[3][1]);
        }
        float s4[4][4];
#pragma unroll
        for (int i = 0; i < 4; i++) {
            float2 a = up2(sp[i][0]), bb = up2(sp[i][1]);
            s4[i][0] = a.x; s4[i][1] = a.y; s4[i][2] = bb.x; s4[i][3] = bb.y;
        }
#pragma unroll
        for (int rr = 0; rr < 4; rr++) {
            int iG = qt * 64 + ty * 4 + rr;
#pragma unroll
            for (int cc = 0; cc < 4; cc++) {
                int jG = kt * 64 + tx * 4 + cc;
                bool ok = (jG >= iG) && (jG - iG < win);
                s4[rr][cc] = ok ? s4[rr][cc] * 0.125f : -1e30f;
            }
        }
#pragma unroll
        for (int rr = 0; rr < 4; rr++) {
            float mx = fmaxf(fmaxf(s4[rr][0], s4[rr][1]), fmaxf(s4[rr][2], s4[rr][3]));
            mx = fmaxf(mx, __shfl_xor_sync(0xffffffffu, mx, 1));
            mx = fmaxf(mx, __shfl_xor_sync(0xffffffffu, mx, 2));
            mx = fmaxf(mx, __shfl_xor_sync(0xffffffffu, mx, 4));
            mx = fmaxf(mx, __shfl_xor_sync(0xffffffffu, mx, 8));
            float mnew = fmaxf(m[rr], mx);
            float corr = __expf(m[rr] - mnew);
            float rs = 0.f;
#pragma unroll
            for (int cc = 0; cc < 4; cc++) {
                s4[rr][cc] = __expf(s4[rr][cc] - mnew);
                rs += s4[rr][cc];
            }
            rs += __shfl_xor_sync(0xffffffffu, rs, 1);
            rs += __shfl_xor_sync(0xffffffffu, rs, 2);
            rs += __shfl_xor_sync(0xffffffffu, rs, 4);
            rs += __shfl_xor_sync(0xffffffffu, rs, 8);
            l[rr] = l[rr] * corr + rs;
            m[rr] = mnew;
            ull cd = pk2(corr, corr);
            opk[rr][0] = mul2(opk[rr][0], cd);
            opk[rr][1] = mul2(opk[rr][1], cd);
        }
#pragma unroll
        for (int cc = 0; cc < 4; cc++) {
            float4 pv = make_float4(s4[0][cc], s4[1][cc], s4[2][cc], s4[3][cc]);
            *(float4*)&ps[(tx * 4 + cc) * 68 + ty * 4] = pv;
        }
        __syncthreads();
#pragma unroll 8
        for (int j = 0; j < 64; j++) {
            float4 pv = *(float4*)&ps[j * 68 + ty * 4];
            const ull* vp = (const ull*)&vs[j * 68 + tx * 4];
            ull v0 = vp[0], v1 = vp[1];
            ull p0 = pk2(pv.x, pv.x), p1 = pk2(pv.y, pv.y);
            ull p2 = pk2(pv.z, pv.z), p3 = pk2(pv.w, pv.w);
            opk[0][0] = ffma2(p0, v0, opk[0][0]); opk[0][1] = ffma2(p0, v1, opk[0][1]);
            opk[1][0] = ffma2(p1, v0, opk[1][0]); opk[1][1] = ffma2(p1, v1, opk[1][1]);
            opk[2][0] = ffma2(p2, v0, opk[2][0]); opk[2][1] = ffma2(p2, v1, opk[2][1]);
            opk[3][0] = ffma2(p3, v0, opk[3][0]); opk[3][1] = ffma2(p3, v1, opk[3][1]);
        }
    }
    float* ob = g_local + ((size_t)bh * 2048 + qt * 64) * 64;
#pragma unroll
    for (int rr = 0; rr < 4; rr++) {
        float inv = 1.f / l[rr];
        float2 a = up2(opk[rr][0]), bb = up2(opk[rr][1]);
        float4 ov = make_float4(a.x * inv, a.y * inv, bb.x * inv, bb.y * inv);
        *(float4*)&ob[(size_t)(ty * 4 + rr) * 64 + tx * 4] = ov;
    }
}

// ---- GRU scan: one block per (b,h), packed FFMA2 dot products --------------
__global__ __launch_bounds__(256, 1) void gru_kernel(
    const float* __restrict__ Wr, const float* __restrict__ Wz,
    const float* __restrict__ Wn)
{
    const int bh = blockIdx.x;
    const int b = bh / 12, h = bh - b * 12;
    const int tid = threadIdx.x;
    const int j = tid >> 2, c = tid & 3;
    __shared__ float h_sh[64];
    __shared__ float rh_sh[64];

    ull wrp[8], wzp[8], wnp[8];
#pragma unroll
    for (int q = 0; q < 8; q++) {
        int i = c * 16 + q * 2;
        wrp[q] = pk2(Wr[i * 64 + j], Wr[(i + 1) * 64 + j]);
        wzp[q] = pk2(Wz[i * 64 + j], Wz[(i + 1) * 64 + j]);
        wnp[q] = pk2(Wn[i * 64 + j], Wn[(i + 1) * 64 + j]);
    }
    if (tid < 64) h_sh[tid] = 0.f;
    __syncthreads();

    const float* kbase = g_qkv + ((size_t)b * 2048) * 2304 + 768 + h * 64;
    const float* vbase = kbase + 768;
    const float* kurb = g_kur + (size_t)bh * 2048 * 64;
    const float* kunb = g_kun + (size_t)bh * 2048 * 64;
    float* rout = g_rnn + (size_t)bh * 2048 * 64;

    float ktc = kbase[j], vtc = vbase[j], kurc = kurb[j], kunc = kunb[j];

    for (int t = 0; t < 2048; t++) {
        float ktn = 0.f, vtn = 0.f, kurn = 0.f, kunn = 0.f;
        if (t + 1 < 2048) {
            ktn  = kbase[(size_t)(t + 1) * 2304 + j];
            vtn  = vbase[(size_t)(t + 1) * 2304 + j];
            kurn = kurb[(size_t)(t + 1) * 64 + j];
            kunn = kunb[(size_t)(t + 1) * 64 + j];
        }
        ull aR = 0ull, aZ = 0ull;
        const ull* h2 = (const ull*)&h_sh[c * 16];
#pragma unroll
        for (int q = 0; q < 8; q++) {
            ull hp = h2[q];
            aR = ffma2(hp, wrp[q], aR);
            aZ = ffma2(hp, wzp[q], aZ);
        }
        float2 fR = up2(aR), fZ = up2(aZ);
        float accR = fR.x + fR.y, accZ = fZ.x + fZ.y;
        accR += __shfl_xor_sync(0xffffffffu, accR, 1);
        accR += __shfl_xor_sync(0xffffffffu, accR, 2);
        accZ += __shfl_xor_sync(0xffffffffu, accZ, 1);
        accZ += __shfl_xor_sync(0xffffffffu, accZ, 2);
        float r = 1.f / (1.f + __expf(-(accR + kurc)));
        float z = 1.f / (1.f + __expf(-(accZ + ktc)));
        float hj = h_sh[j];
        if (c == 0) rh_sh[j] = r * hj;
        __syncthreads();

        ull aN = 0ull;
        const ull* rh2 = (const ull*)&rh_sh[c * 16];
#pragma unroll
        for (int q = 0; q < 8; q++)
            aN = ffma2(rh2[q], wnp[q], aN);
        float2 fN = up2(aN);
        float accN = fN.x + fN.y;
        accN += __shfl_xor_sync(0xffffffffu, accN, 1);
        accN += __shfl_xor_sync(0xffffffffu, accN, 2);
        float n = tanhf(accN + kunc);
        float hnew = (1.f - z) * hj + z * (n * vtc);
        if (c == 0) {
            h_sh[j] = hnew;
            rout[(size_t)t * 64 + j] = hnew;
        }
        __syncthreads();

        ktc = ktn; vtc = vtn; kurc = kurn; kunc = kunn;
    }
}

// ---- gate: alpha = sigmoid(x @ gate_w + gate_b) ----------------------------
__global__ __launch_bounds__(256) void gate_kernel(
    const float* __restrict__ x, const float* __restrict__ gw,
    const float* __restrict__ gb)
{
    int gid = blockIdx.x * 256 + threadIdx.x;
    if (gid >= 4 * 2048 * 12) return;
    int h = gid % 12;
    int bt = gid / 12;
    const float* xr = x + (size_t)bt * 768;
    float acc = gb[h];
#pragma unroll 4
    for (int i = 0; i < 768; i++)
        acc = fmaf(__ldg(xr + i), __ldg(gw + (size_t)i * 12 + h), acc);
    g_alpha[gid] = 1.f / (1.f + __expf(-acc));
}

// ---- combine: y = alpha*local + (1-alpha)*rnn, heads -> [B,T,C] ------------
__global__ __launch_bounds__(256) void combine_kernel()
{
    int gid = blockIdx.x * 256 + threadIdx.x;
    if (gid >= 4 * 2048 * 192) return;      // B*T*C/4
    int c4 = gid % 192;
    int bt = gid / 192;
    int h = c4 >> 4, d4 = c4 & 15;
    int b = bt >> 11, t = bt & 2047;
    float a = g_alpha[bt * 12 + h];
    size_t idx = ((size_t)(b * 12 + h) * 2048 + t) * 64 + d4 * 4;
    float4 lo = *(const float4*)(g_local + idx);
    float4 rn = *(const float4*)(g_rnn + idx);
    float4 o;
    o.x = a * lo.x + (1.f - a) * rn.x;
    o.y = a * lo.y + (1.f - a) * rn.y;
    o.z = a * lo.z + (1.f - a) * rn.z;
    o.w = a * lo.w + (1.f - a) * rn.w;
    *(float4*)(g_y + (size_t)bt * 768 + c4 * 4) = o;
}

extern "C" void kernel_launch(void* const* d_in, const int* in_sizes, int n_in,
                              void* d_out, int out_size) {
    const float* x      = (const float*)d_in[0];
    const void*  winp   = d_in[1];
    const float* qkv_w  = (const float*)d_in[2];
    const float* qkv_b  = (const float*)d_in[3];
    const float* proj_w = (const float*)d_in[4];
    const float* proj_b = (const float*)d_in[5];
    const float* Wr     = (const float*)d_in[6];
    const float* Ur     = (const float*)d_in[7];
    const float* Wz     = (const float*)d_in[8];
    const float* Wn     = (const float*)d_in[9];
    const float* Un     = (const float*)d_in[10];
    const float* gate_w = (const float*)d_in[11];
    const float* gate_b = (const float*)d_in[12];
    float* out = (float*)d_out;

    float* qkv_g;   cudaGetSymbolAddress((void**)&qkv_g,  g_qkv);
    float* y_g;     cudaGetSymbolAddress((void**)&y_g,    g_y);

    cudaFuncSetAttribute(attn_kernel,
        cudaFuncAttributeMaxDynamicSharedMemorySize, 4 * 64 * 68 * 4);

    win_kernel<<<1, 1>>>(winp);

    // qkv = x @ qkv_w + qkv_b : [8192,2304]
    sgemm_bias<<<dim3(18, 64), 256>>>(x, qkv_w, qkv_b, qkv_g, 8192, 2304, 768);

    // hoisted k@Ur, k@Un
    ku_kernel<<<dim3(32, 48), 256>>>(Ur, Un);

    // windowed attention
    attn_kernel<<<dim3(32, 48), 256, 4 * 64 * 68 * 4>>>();

    // recurrent scan
    gru_kernel<<<48, 256>>>(Wr, Wz, Wn);

    // gate
    gate_kernel<<<384, 256>>>(x, gate_w, gate_b);

    // mix + head-merge
    combine_kernel<<<6144, 256>>>();

    // out = y @ proj_w + proj_b : [8192,768]
    sgemm_bias<<<dim3(6, 64), 256>>>(y_g, proj_w, proj_b, out, 8192, 768, 768);
}

// round 7
// speedup vs baseline: 1.1130x; 1.1130x over previous
#include <cuda_runtime.h>
#include <cuda_bf16.h>
#include <cstdint>

// B=4, T=2048, C=768, H=12, D=64, 3C=2304, BH=48

typedef unsigned long long ull;

__device__ float g_qkv  [4*2048*2304];   // [B,T,3C]
__device__ float g_kur  [48*2048*64];    // k @ Ur   [B*H,T,D]
__device__ float g_kun  [48*2048*64];    // k @ Un
__device__ float g_local[48*2048*64];    // attention out
__device__ float g_rnn  [48*2048*64];    // scan out
__device__ float g_alpha[4*2048*12];     // gate [B*T,H]
__device__ float g_y    [4*2048*768];    // mixed
__device__ int   g_win;

// ---- packed f32x2 helpers (kept for attn/gru where they measured >= neutral)
__device__ __forceinline__ ull ffma2(ull a, ull b, ull c) {
    ull d;
    asm("fma.rn.f32x2 %0, %1, %2, %3;" : "=l"(d) : "l"(a), "l"(b), "l"(c));
    return d;
}
__device__ __forceinline__ ull mul2(ull a, ull b) {
    ull d;
    asm("mul.rn.f32x2 %0, %1, %2;" : "=l"(d) : "l"(a), "l"(b));
    return d;
}
__device__ __forceinline__ ull pk2(float x, float y) {
    ull r;
    asm("mov.b64 %0, {%1, %2};" : "=l"(r) : "f"(x), "f"(y));
    return r;
}
__device__ __forceinline__ float2 up2(ull v) {
    float2 f;
    asm("mov.b64 {%0, %1}, %2;" : "=f"(f.x), "=f"(f.y) : "l"(v));
    return f;
}

// ---- tensor-core primitives -------------------------------------------------
#define LDSM4(r, addr) \
    asm volatile("ldmatrix.sync.aligned.m8n8.x4.shared.b16 {%0,%1,%2,%3}, [%4];" \
        : "=r"((r)[0]), "=r"((r)[1]), "=r"((r)[2]), "=r"((r)[3]) : "r"(addr))
#define LDSM4T(r, addr) \
    asm volatile("ldmatrix.sync.aligned.m8n8.x4.trans.shared.b16 {%0,%1,%2,%3}, [%4];" \
        : "=r"((r)[0]), "=r"((r)[1]), "=r"((r)[2]), "=r"((r)[3]) : "r"(addr))
#define MMA16816(d, a, b0v, b1v) \
    asm volatile("mma.sync.aligned.m16n8k16.row.col.f32.bf16.bf16.f32 " \
        "{%0,%1,%2,%3}, {%4,%5,%6,%7}, {%8,%9}, {%0,%1,%2,%3};" \
        : "+f"((d)[0]), "+f"((d)[1]), "+f"((d)[2]), "+f"((d)[3]) \
        : "r"((a)[0]), "r"((a)[1]), "r"((a)[2]), "r"((a)[3]), "r"(b0v), "r"(b1v))

__device__ __forceinline__ uint32_t smem_u32(const void* p) {
    return (uint32_t)__cvta_generic_to_shared(p);
}

// ---- window scalar normalization -------------------------------------------
__global__ void win_kernel(const void* wp) {
    int v = *(const int*)wp;
    if (v < 1 || v > 4096) {
        float f = *(const float*)wp;
        int vf = (int)f;
        if (vf >= 1 && vf <= 4096) v = vf; else v = 256;
    }
    g_win = v;
}

// ---- split-bf16 tensor-core GEMM + bias ------------------------------------
// C[M,N] = A[M,K]@B[K,N] + bias.  A,B fp32; split each into bf16 hi+lo and
// accumulate Ah@Bh + Ah@Bl + Al@Bh with mma.sync m16n8k16 (fp32 accum).
// Tile 128x128, BK=16, 256 threads = 8 warps (4x2), warp tile 32x64.
__global__ __launch_bounds__(256) void gemm_bf16x2(
    const float* __restrict__ A, const float* __restrict__ Bm,
    const float* __restrict__ bias, float* __restrict__ C,
    int M, int N, int K)
{
    __shared__ __align__(16) __nv_bfloat16 Ah[128][24];  // [m][k], stride 24 (48B)
    __shared__ __align__(16) __nv_bfloat16 Al[128][24];
    __shared__ __align__(16) __nv_bfloat16 Bh[16][136];  // [k][n], stride 136 (272B)
    __shared__ __align__(16) __nv_bfloat16 Bl[16][136];

    const int tid  = threadIdx.x;
    const int bm   = blockIdx.y * 128, bn = blockIdx.x * 128;
    const int warp = tid >> 5, lane = tid & 31;
    const int wm   = (warp >> 1) * 32;   // warp M offset within tile
    const int wn   = (warp & 1) * 64;    // warp N offset

    float acc[2][8][4];                  // [m-frag][n-frag][reg]
#pragma unroll
    for (int i = 0; i < 2; i++)
#pragma unroll
        for (int j = 0; j < 8; j++)
#pragma unroll
            for (int r = 0; r < 4; r++) acc[i][j][r] = 0.f;

    // ldmatrix base addresses (per-lane, constant across k-tiles)
    const int a_row = lane & 15;         // lanes 0-15: m 0..15 ; 16-31 repeat
    const int a_k   = (lane >> 4) * 8;   // second 16 lanes: k-half 8..15
    const int b_row = lane & 15;         // k row 0..15
    const int b_n   = (lane >> 4) * 8;   // second 16 lanes: n-half

    for (int k0 = 0; k0 < K; k0 += 16) {
        // --- load + split A tile (128 x 16) ---
#pragma unroll
        for (int i = 0; i < 2; i++) {
            int s = i * 256 + tid;
            int r = s >> 2, kk = (s & 3) << 2;
            float4 a = *(const float4*)(A + (size_t)(bm + r) * K + k0 + kk);
            __nv_bfloat16 h0 = __float2bfloat16(a.x);
            __nv_bfloat16 h1 = __float2bfloat16(a.y);
            __nv_bfloat16 h2 = __float2bfloat16(a.z);
            __nv_bfloat16 h3 = __float2bfloat16(a.w);
            __nv_bfloat16 l0 = __float2bfloat16(a.x - __bfloat162float(h0));
            __nv_bfloat16 l1 = __float2bfloat16(a.y - __bfloat162float(h1));
            __nv_bfloat16 l2 = __float2bfloat16(a.z - __bfloat162float(h2));
            __nv_bfloat16 l3 = __float2bfloat16(a.w - __bfloat162float(h3));
            *(__nv_bfloat162*)&Ah[r][kk]     = __halves2bfloat162(h0, h1);
            *(__nv_bfloat162*)&Ah[r][kk + 2] = __halves2bfloat162(h2, h3);
            *(__nv_bfloat162*)&Al[r][kk]     = __halves2bfloat162(l0, l1);
            *(__nv_bfloat162*)&Al[r][kk + 2] = __halves2bfloat162(l2, l3);
        }
        // --- load + split B tile (16 x 128) ---
#pragma unroll
        for (int i = 0; i < 2; i++) {
            int s = i * 256 + tid;
            int r = s >> 5, cc = (s & 31) << 2;
            float4 b = *(const float4*)(Bm + (size_t)(k0 + r) * N + bn + cc);
            __nv_bfloat16 h0 = __float2bfloat16(b.x);
            __nv_bfloat16 h1 = __float2bfloat16(b.y);
            __nv_bfloat16 h2 = __float2bfloat16(b.z);
            __nv_bfloat16 h3 = __float2bfloat16(b.w);
            __nv_bfloat16 l0 = __float2bfloat16(b.x - __bfloat162float(h0));
            __nv_bfloat16 l1 = __float2bfloat16(b.y - __bfloat162float(h1));
            __nv_bfloat16 l2 = __float2bfloat16(b.z - __bfloat162float(h2));
            __nv_bfloat16 l3 = __float2bfloat16(b.w - __bfloat162float(h3));
            *(__nv_bfloat162*)&Bh[r][cc]     = __halves2bfloat162(h0, h1);
            *(__nv_bfloat162*)&Bh[r][cc + 2] = __halves2bfloat162(h2, h3);
            *(__nv_bfloat162*)&Bl[r][cc]     = __halves2bfloat162(l0, l1);
            *(__nv_bfloat162*)&Bl[r][cc + 2] = __halves2bfloat162(l2, l3);
        }
        __syncthreads();

        // --- A fragments (hi & lo, two m16 frags each) ---
        uint32_t ah[2][4], al[2][4];
#pragma unroll
        for (int fm = 0; fm < 2; fm++) {
            LDSM4(ah[fm], smem_u32(&Ah[wm + fm * 16 + a_row][a_k]));
            LDSM4(al[fm], smem_u32(&Al[wm + fm * 16 + a_row][a_k]));
        }
        // --- per 16-wide n group: load B frags, do 12 mma ---
#pragma unroll
        for (int jn = 0; jn < 4; jn++) {
            uint32_t bh4[4], bl4[4];
            LDSM4T(bh4, smem_u32(&Bh[b_row][wn + jn * 16 + b_n]));
            LDSM4T(bl4, smem_u32(&Bl[b_row][wn + jn * 16 + b_n]));
#pragma unroll
            for (int fm = 0; fm < 2; fm++)
#pragma unroll
                for (int hf = 0; hf < 2; hf++)
                    MMA16816(acc[fm][jn * 2 + hf], ah[fm], bh4[hf * 2], bh4[hf * 2 + 1]);
#pragma unroll
            for (int fm = 0; fm < 2; fm++)
#pragma unroll
                for (int hf = 0; hf < 2; hf++)
                    MMA16816(acc[fm][jn * 2 + hf], ah[fm], bl4[hf * 2], bl4[hf * 2 + 1]);
#pragma unroll
            for (int fm = 0; fm < 2; fm++)
#pragma unroll
                for (int hf = 0; hf < 2; hf++)
                    MMA16816(acc[fm][jn * 2 + hf], al[fm], bh4[hf * 2], bh4[hf * 2 + 1]);
        }
        __syncthreads();
    }

    // --- epilogue: D frag (m16n8): c0,c1 row g cols 2t,2t+1 ; c2,c3 row g+8 ---
    const int g = lane >> 2, tq = lane & 3;
#pragma unroll
    for (int fm = 0; fm < 2; fm++) {
#pragma unroll
        for (int nf = 0; nf < 8; nf++) {
            int col = bn + wn + nf * 8 + tq * 2;
            float2 bv = *(const float2*)(bias + col);
            int row0 = bm + wm + fm * 16 + g;
            float2 o0 = make_float2(acc[fm][nf][0] + bv.x, acc[fm][nf][1] + bv.y);
            float2 o1 = make_float2(acc[fm][nf][2] + bv.x, acc[fm][nf][3] + bv.y);
            *(float2*)(C + (size_t)row0 * N + col) = o0;
            *(float2*)(C + (size_t)(row0 + 8) * N + col) = o1;
        }
    }
}

// ---- kUr/kUn: per (b,h), 64-row time tiles ---------------------------------
__global__ __launch_bounds__(256) void ku_kernel(
    const float* __restrict__ Ur, const float* __restrict__ Un)
{
    __shared__ float ks[64][64];
    __shared__ float ur[64][64];
    __shared__ float un[64][64];
    const int t64 = blockIdx.x, bh = blockIdx.y;
    const int b = bh / 12, h = bh - b * 12;
    const int tid = threadIdx.x;
#pragma unroll
    for (int i = 0; i < 4; i++) {
        int s = i * 256 + tid;
        ((float4*)ur)[s] = ((const float4*)Ur)[s];
        ((float4*)un)[s] = ((const float4*)Un)[s];
    }
    const float* kb = g_qkv + ((size_t)(b * 2048 + t64 * 64)) * 2304 + 768 + h * 64;
#pragma unroll
    for (int q = 0; q < 4; q++) {
        int s = q * 256 + tid;
        int r = s >> 4, d0 = (s & 15) << 2;
        *(float4*)&ks[r][d0] = *(const float4*)(kb + (size_t)r * 2304 + d0);
    }
    __syncthreads();
    const int tx = tid & 15, ty = tid >> 4;
    ull ar[4][2], an[4][2];
#pragma unroll
    for (int i = 0; i < 4; i++)
#pragma unroll
        for (int j = 0; j < 2; j++) { ar[i][j] = 0ull; an[i][j] = 0ull; }

    for (int i0 = 0; i0 < 64; i0 += 4) {
        float krr[4][4];
#pragma unroll
        for (int rr = 0; rr < 4; rr++)
            *(float4*)&krr[rr][0] = *(const float4*)&ks[ty * 4 + rr][i0];
#pragma unroll
        for (int q = 0; q < 4; q++) {
            const ull* uR2 = (const ull*)&ur[i0 + q][tx * 4];
            const ull* uN2 = (const ull*)&un[i0 + q][tx * 4];
            ull uR0 = uR2[0], uR1 = uR2[1], uN0 = uN2[0], uN1 = uN2[1];
#pragma unroll
            for (int rr = 0; rr < 4; rr++) {
                ull kd = pk2(krr[rr][q], krr[rr][q]);
                ar[rr][0] = ffma2(kd, uR0, ar[rr][0]);
                ar[rr][1] = ffma2(kd, uR1, ar[rr][1]);
                an[rr][0] = ffma2(kd, uN0, an[rr][0]);
                an[rr][1] = ffma2(kd, uN1, an[rr][1]);
            }
        }
    }
    float* outR = g_kur + ((size_t)bh * 2048 + t64 * 64) * 64;
    float* outN = g_kun + ((size_t)bh * 2048 + t64 * 64) * 64;
#pragma unroll
    for (int rr = 0; rr < 4; rr++) {
        float2 r0 = up2(ar[rr][0]), r1 = up2(ar[rr][1]);
        float2 n0 = up2(an[rr][0]), n1 = up2(an[rr][1]);
        float4 oR = make_float4(r0.x, r0.y, r1.x, r1.y);
        float4 oN = make_float4(n0.x, n0.y, n1.x, n1.y);
        *(float4*)&outR[(size_t)(ty * 4 + rr) * 64 + tx * 4] = oR;
        *(float4*)&outN[(size_t)(ty * 4 + rr) * 64 + tx * 4] = oN;
    }
}

// ---- windowed flash attention, 64x64 tiles, FFMA2 mainloops ----------------
__global__ __launch_bounds__(256) void attn_kernel()
{
    extern __shared__ float sm[];
    float* qs = sm;                  // [d][r] stride 68
    float* ks = qs + 64 * 68;        // [d][j]
    float* vs = ks + 64 * 68;        // [j][d]
    float* ps = vs + 64 * 68;        // [j][r]
    const int qt = blockIdx.x, bh = blockIdx.y;
    const int b = bh / 12, h = bh - b * 12;
    const int tid = threadIdx.x;
    const int tx = tid & 15, ty = tid >> 4;
    const int win = g_win;

    const float* qbase = g_qkv + ((size_t)(b * 2048 + qt * 64)) * 2304 + h * 64;
#pragma unroll
    for (int q = 0; q < 4; q++) {
        int s = q * 256 + tid;
        int r = s >> 4, d0 = (s & 15) << 2;
        float4 v = *(const float4*)(qbase + (size_t)r * 2304 + d0);
        qs[(d0 + 0) * 68 + r] = v.x; qs[(d0 + 1) * 68 + r] = v.y;
        qs[(d0 + 2) * 68 + r] = v.z; qs[(d0 + 3) * 68 + r] = v.w;
    }
    ull opk[4][2];
    float m[4], l[4];
#pragma unroll
    for (int i = 0; i < 4; i++) {
        m[i] = -1e30f; l[i] = 0.f;
        opk[i][0] = 0ull; opk[i][1] = 0ull;
    }
    int ktmax = (qt * 64 + 63 + win - 1) >> 6;
    if (ktmax > 31) ktmax = 31;

    for (int kt = qt; kt <= ktmax; kt++) {
        __syncthreads();
        const float* kb = g_qkv + ((size_t)(b * 2048 + kt * 64)) * 2304 + 768 + h * 64;
        const float* vb = kb + 768;
#pragma unroll
        for (int q = 0; q < 4; q++) {
            int s = q * 256 + tid;
            int r = s >> 4, d0 = (s & 15) << 2;
            float4 kv = *(const float4*)(kb + (size_t)r * 2304 + d0);
            ks[(d0 + 0) * 68 + r] = kv.x; ks[(d0 + 1) * 68 + r] = kv.y;
            ks[(d0 + 2) * 68 + r] = kv.z; ks[(d0 + 3) * 68 + r] = kv.w;
            *(float4*)&vs[r * 68 + d0] = *(const float4*)(vb + (size_t)r * 2304 + d0);
        }
        __syncthreads();

        ull sp[4][2];
#pragma unroll
        for (int i = 0; i < 4; i++) { sp[i][0] = 0ull; sp[i][1] = 0ull; }
#pragma unroll 8
        for (int d = 0; d < 64; d++) {
            float4 qv = *(float4*)&qs[d * 68 + ty * 4];
            const ull* kp = (const ull*)&ks[d * 68 + tx * 4];
            ull k0 = kp[0], k1 = kp[1];
            ull q0 = pk2(qv.x, qv.x), q1 = pk2(qv.y, qv.y);
            ull q2 = pk2(qv.z, qv.z), q3 = pk2(qv.w, qv.w);
            sp[0][0] = ffma2(q0, k0, sp[0][0]); sp[0][1] = ffma2(q0, k1, sp[0][1]);
            sp[1][0] = ffma2(q1, k0, sp[1][0]); sp[1][1] = ffma2(q1, k1, sp[1][1]);
            sp[2][0] = ffma2(q2, k0, sp[2][0]); sp[2][1] = ffma2(q2, k1, sp[2][1]);
            sp[3][0] = ffma2(q3, k0, sp[3][0]); sp[3][1] = ffma2(q3, k1, sp[3][1]);
        }
        float s4[4][4];
#pragma unroll
        for (int i = 0; i < 4; i++) {
            float2 a = up2(sp[i][0]), bb = up2(sp[i][1]);
            s4[i][0] = a.x; s4[i][1] = a.y; s4[i][2] = bb.x; s4[i][3] = bb.y;
        }
#pragma unroll
        for (int rr = 0; rr < 4; rr++) {
            int iG = qt * 64 + ty * 4 + rr;
#pragma unroll
            for (int cc = 0; cc < 4; cc++) {
                int jG = kt * 64 + tx * 4 + cc;
                bool ok = (jG >= iG) && (jG - iG < win);
                s4[rr][cc] = ok ? s4[rr][cc] * 0.125f : -1e30f;
            }
        }
#pragma unroll
        for (int rr = 0; rr < 4; rr++) {
            float mx = fmaxf(fmaxf(s4[rr][0], s4[rr][1]), fmaxf(s4[rr][2], s4[rr][3]));
            mx = fmaxf(mx, __shfl_xor_sync(0xffffffffu, mx, 1));
            mx = fmaxf(mx, __shfl_xor_sync(0xffffffffu, mx, 2));
            mx = fmaxf(mx, __shfl_xor_sync(0xffffffffu, mx, 4));
            mx = fmaxf(mx, __shfl_xor_sync(0xffffffffu, mx, 8));
            float mnew = fmaxf(m[rr], mx);
            float corr = __expf(m[rr] - mnew);
            float rs = 0.f;
#pragma unroll
            for (int cc = 0; cc < 4; cc++) {
                s4[rr][cc] = __expf(s4[rr][cc] - mnew);
                rs += s4[rr][cc];
            }
            rs += __shfl_xor_sync(0xffffffffu, rs, 1);
            rs += __shfl_xor_sync(0xffffffffu, rs, 2);
            rs += __shfl_xor_sync(0xffffffffu, rs, 4);
            rs += __shfl_xor_sync(0xffffffffu, rs, 8);
            l[rr] = l[rr] * corr + rs;
            m[rr] = mnew;
            ull cd = pk2(corr, corr);
            opk[rr][0] = mul2(opk[rr][0], cd);
            opk[rr][1] = mul2(opk[rr][1], cd);
        }
#pragma unroll
        for (int cc = 0; cc < 4; cc++) {
            float4 pv = make_float4(s4[0][cc], s4[1][cc], s4[2][cc], s4[3][cc]);
            *(float4*)&ps[(tx * 4 + cc) * 68 + ty * 4] = pv;
        }
        __syncthreads();
#pragma unroll 8
        for (int j = 0; j < 64; j++) {
            float4 pv = *(float4*)&ps[j * 68 + ty * 4];
            const ull* vp = (const ull*)&vs[j * 68 + tx * 4];
            ull v0 = vp[0], v1 = vp[1];
            ull p0 = pk2(pv.x, pv.x), p1 = pk2(pv.y, pv.y);
            ull p2 = pk2(pv.z, pv.z), p3 = pk2(pv.w, pv.w);
            opk[0][0] = ffma2(p0, v0, opk[0][0]); opk[0][1] = ffma2(p0, v1, opk[0][1]);
            opk[1][0] = ffma2(p1, v0, opk[1][0]); opk[1][1] = ffma2(p1, v1, opk[1][1]);
            opk[2][0] = ffma2(p2, v0, opk[2][0]); opk[2][1] = ffma2(p2, v1, opk[2][1]);
            opk[3][0] = ffma2(p3, v0, opk[3][0]); opk[3][1] = ffma2(p3, v1, opk[3][1]);
        }
    }
    float* ob = g_local + ((size_t)bh * 2048 + qt * 64) * 64;
#pragma unroll
    for (int rr = 0; rr < 4; rr++) {
        float inv = 1.f / l[rr];
        float2 a = up2(opk[rr][0]), bb = up2(opk[rr][1]);
        float4 ov = make_float4(a.x * inv, a.y * inv, bb.x * inv, bb.y * inv);
        *(float4*)&ob[(size_t)(ty * 4 + rr) * 64 + tx * 4] = ov;
    }
}

// ---- GRU scan: one block per (b,h), packed FFMA2 dot products --------------
__global__ __launch_bounds__(256, 1) void gru_kernel(
    const float* __restrict__ Wr, const float* __restrict__ Wz,
    const float* __restrict__ Wn)
{
    const int bh = blockIdx.x;
    const int b = bh / 12, h = bh - b * 12;
    const int tid = threadIdx.x;
    const int j = tid >> 2, c = tid & 3;
    __shared__ float h_sh[64];
    __shared__ float rh_sh[64];

    ull wrp[8], wzp[8], wnp[8];
#pragma unroll
    for (int q = 0; q < 8; q++) {
        int i = c * 16 + q * 2;
        wrp[q] = pk2(Wr[i * 64 + j], Wr[(i + 1) * 64 + j]);
        wzp[q] = pk2(Wz[i * 64 + j], Wz[(i + 1) * 64 + j]);
        wnp[q] = pk2(Wn[i * 64 + j], Wn[(i + 1) * 64 + j]);
    }
    if (tid < 64) h_sh[tid] = 0.f;
    __syncthreads();

    const float* kbase = g_qkv + ((size_t)b * 2048) * 2304 + 768 + h * 64;
    const float* vbase = kbase + 768;
    const float* kurb = g_kur + (size_t)bh * 2048 * 64;
    const float* kunb = g_kun + (size_t)bh * 2048 * 64;
    float* rout = g_rnn + (size_t)bh * 2048 * 64;

    float ktc = kbase[j], vtc = vbase[j], kurc = kurb[j], kunc = kunb[j];

    for (int t = 0; t < 2048; t++) {
        float ktn = 0.f, vtn = 0.f, kurn = 0.f, kunn = 0.f;
        if (t + 1 < 2048) {
            ktn  = kbase[(size_t)(t + 1) * 2304 + j];
            vtn  = vbase[(size_t)(t + 1) * 2304 + j];
            kurn = kurb[(size_t)(t + 1) * 64 + j];
            kunn = kunb[(size_t)(t + 1) * 64 + j];
        }
        ull aR = 0ull, aZ = 0ull;
        const ull* h2 = (const ull*)&h_sh[c * 16];
#pragma unroll
        for (int q = 0; q < 8; q++) {
            ull hp = h2[q];
            aR = ffma2(hp, wrp[q], aR);
            aZ = ffma2(hp, wzp[q], aZ);
        }
        float2 fR = up2(aR), fZ = up2(aZ);
        float accR = fR.x + fR.y, accZ = fZ.x + fZ.y;
        accR += __shfl_xor_sync(0xffffffffu, accR, 1);
        accR += __shfl_xor_sync(0xffffffffu, accR, 2);
        accZ += __shfl_xor_sync(0xffffffffu, accZ, 1);
        accZ += __shfl_xor_sync(0xffffffffu, accZ, 2);
        float r = 1.f / (1.f + __expf(-(accR + kurc)));
        float z = 1.f / (1.f + __expf(-(accZ + ktc)));
        float hj = h_sh[j];
        if (c == 0) rh_sh[j] = r * hj;
        __syncthreads();

        ull aN = 0ull;
        const ull* rh2 = (const ull*)&rh_sh[c * 16];
#pragma unroll
        for (int q = 0; q < 8; q++)
            aN = ffma2(rh2[q], wnp[q], aN);
        float2 fN = up2(aN);
        float accN = fN.x + fN.y;
        accN += __shfl_xor_sync(0xffffffffu, accN, 1);
        accN += __shfl_xor_sync(0xffffffffu, accN, 2);
        float n = tanhf(accN + kunc);
        float hnew = (1.f - z) * hj + z * (n * vtc);
        if (c == 0) {
            h_sh[j] = hnew;
            rout[(size_t)t * 64 + j] = hnew;
        }
        __syncthreads();

        ktc = ktn; vtc = vtn; kurc = kurn; kunc = kunn;
    }
}

// ---- gate: alpha = sigmoid(x @ gate_w + gate_b) ----------------------------
__global__ __launch_bounds__(256) void gate_kernel(
    const float* __restrict__ x, const float* __restrict__ gw,
    const float* __restrict__ gb)
{
    int gid = blockIdx.x * 256 + threadIdx.x;
    if (gid >= 4 * 2048 * 12) return;
    int h = gid % 12;
    int bt = gid / 12;
    const float* xr = x + (size_t)bt * 768;
    float acc = gb[h];
#pragma unroll 4
    for (int i = 0; i < 768; i++)
        acc = fmaf(__ldg(xr + i), __ldg(gw + (size_t)i * 12 + h), acc);
    g_alpha[gid] = 1.f / (1.f + __expf(-acc));
}

// ---- combine: y = alpha*local + (1-alpha)*rnn, heads -> [B,T,C] ------------
__global__ __launch_bounds__(256) void combine_kernel()
{
    int gid = blockIdx.x * 256 + threadIdx.x;
    if (gid >= 4 * 2048 * 192) return;      // B*T*C/4
    int c4 = gid % 192;
    int bt = gid / 192;
    int h = c4 >> 4, d4 = c4 & 15;
    int b = bt >> 11, t = bt & 2047;
    float a = g_alpha[bt * 12 + h];
    size_t idx = ((size_t)(b * 12 + h) * 2048 + t) * 64 + d4 * 4;
    float4 lo = *(const float4*)(g_local + idx);
    float4 rn = *(const float4*)(g_rnn + idx);
    float4 o;
    o.x = a * lo.x + (1.f - a) * rn.x;
    o.y = a * lo.y + (1.f - a) * rn.y;
    o.z = a * lo.z + (1.f - a) * rn.z;
    o.w = a * lo.w + (1.f - a) * rn.w;
    *(float4*)(g_y + (size_t)bt * 768 + c4 * 4) = o;
}

extern "C" void kernel_launch(void* const* d_in, const int* in_sizes, int n_in,
                              void* d_out, int out_size) {
    const float* x      = (const float*)d_in[0];
    const void*  winp   = d_in[1];
    const float* qkv_w  = (const float*)d_in[2];
    const float* qkv_b  = (const float*)d_in[3];
    const float* proj_w = (const float*)d_in[4];
    const float* proj_b = (const float*)d_in[5];
    const float* Wr     = (const float*)d_in[6];
    const float* Ur     = (const float*)d_in[7];
    const float* Wz     = (const float*)d_in[8];
    const float* Wn     = (const float*)d_in[9];
    const float* Un     = (const float*)d_in[10];
    const float* gate_w = (const float*)d_in[11];
    const float* gate_b = (const float*)d_in[12];
    float* out = (float*)d_out;

    float* qkv_g;   cudaGetSymbolAddress((void**)&qkv_g,  g_qkv);
    float* y_g;     cudaGetSymbolAddress((void**)&y_g,    g_y);

    cudaFuncSetAttribute(attn_kernel,
        cudaFuncAttributeMaxDynamicSharedMemorySize, 4 * 64 * 68 * 4);

    win_kernel<<<1, 1>>>(winp);

    // qkv = x @ qkv_w + qkv_b : [8192,2304]  (split-bf16 tensor cores)
    gemm_bf16x2<<<dim3(18, 64), 256>>>(x, qkv_w, qkv_b, qkv_g, 8192, 2304, 768);

    // hoisted k@Ur, k@Un
    ku_kernel<<<dim3(32, 48), 256>>>(Ur, Un);

    // windowed attention
    attn_kernel<<<dim3(32, 48), 256, 4 * 64 * 68 * 4>>>();

    // recurrent scan
    gru_kernel<<<48, 256>>>(Wr, Wz, Wn);

    // gate
    gate_kernel<<<384, 256>>>(x, gate_w, gate_b);

    // mix + head-merge
    combine_kernel<<<6144, 256>>>();

    // out = y @ proj_w + proj_b : [8192,768]  (split-bf16 tensor cores)
    gemm_bf16x2<<<dim3(6, 64), 256>>>(y_g, proj_w, proj_b, out, 8192, 768, 768);
}

// round 9
// speedup vs baseline: 1.1316x; 1.0166x over previous
#include <cuda_runtime.h>
#include <cuda_bf16.h>
#include <cstdint>

// B=4, T=2048, C=768, H=12, D=64, 3C=2304, BH=48

typedef unsigned long long ull;

__device__ float g_qkv  [4*2048*2304];   // [B,T,3C]
__device__ float g_kur  [48*2048*64];
__device__ float g_kun  [48*2048*64];
__device__ float g_local[48*2048*64];
__device__ float g_rnn  [48*2048*64];
__device__ float g_alpha[4*2048*12];
__device__ float g_y    [4*2048*768];
__device__ int   g_win;

// bf16 hi/lo split buffers (pre-converted once per launch)
__device__ __nv_bfloat16 g_xh [4*2048*768];
__device__ __nv_bfloat16 g_xl [4*2048*768];
__device__ __nv_bfloat16 g_wqh[768*2304];
__device__ __nv_bfloat16 g_wql[768*2304];
__device__ __nv_bfloat16 g_yh [4*2048*768];
__device__ __nv_bfloat16 g_yl [4*2048*768];
__device__ __nv_bfloat16 g_wph[768*768];
__device__ __nv_bfloat16 g_wpl[768*768];

// ---- packed f32x2 helpers ---------------------------------------------------
__device__ __forceinline__ ull ffma2(ull a, ull b, ull c) {
    ull d;
    asm("fma.rn.f32x2 %0, %1, %2, %3;" : "=l"(d) : "l"(a), "l"(b), "l"(c));
    return d;
}
__device__ __forceinline__ ull mul2(ull a, ull b) {
    ull d;
    asm("mul.rn.f32x2 %0, %1, %2;" : "=l"(d) : "l"(a), "l"(b));
    return d;
}
__device__ __forceinline__ ull pk2(float x, float y) {
    ull r;
    asm("mov.b64 %0, {%1, %2};" : "=l"(r) : "f"(x), "f"(y));
    return r;
}
__device__ __forceinline__ float2 up2(ull v) {
    float2 f;
    asm("mov.b64 {%0, %1}, %2;" : "=f"(f.x), "=f"(f.y) : "l"(v));
    return f;
}

// ---- tensor-core / async primitives ----------------------------------------
#define LDSM4(r, addr) \
    asm volatile("ldmatrix.sync.aligned.m8n8.x4.shared.b16 {%0,%1,%2,%3}, [%4];" \
        : "=r"((r)[0]), "=r"((r)[1]), "=r"((r)[2]), "=r"((r)[3]) : "r"(addr))
#define LDSM4T(r, addr) \
    asm volatile("ldmatrix.sync.aligned.m8n8.x4.trans.shared.b16 {%0,%1,%2,%3}, [%4];" \
        : "=r"((r)[0]), "=r"((r)[1]), "=r"((r)[2]), "=r"((r)[3]) : "r"(addr))
#define MMA16816(d, a, b0v, b1v) \
    asm volatile("mma.sync.aligned.m16n8k16.row.col.f32.bf16.bf16.f32 " \
        "{%0,%1,%2,%3}, {%4,%5,%6,%7}, {%8,%9}, {%0,%1,%2,%3};" \
        : "+f"((d)[0]), "+f"((d)[1]), "+f"((d)[2]), "+f"((d)[3]) \
        : "r"((a)[0]), "r"((a)[1]), "r"((a)[2]), "r"((a)[3]), "r"(b0v), "r"(b1v))
#define CP16(dst, src) \
    asm volatile("cp.async.cg.shared.global [%0], [%1], 16;" :: "r"(dst), "l"(src))
#define CP_COMMIT() asm volatile("cp.async.commit_group;" ::: "memory")
#define CP_WAIT0()  asm volatile("cp.async.wait_group 0;" ::: "memory")
#define CP_WAIT1()  asm volatile("cp.async.wait_group 1;" ::: "memory")

__device__ __forceinline__ uint32_t smem_u32(const void* p) {
    return (uint32_t)__cvta_generic_to_shared(p);
}

// ---- window scalar normalization -------------------------------------------
__global__ void win_kernel(const void* wp) {
    int v = *(const int*)wp;
    if (v < 1 || v > 4096) {
        float f = *(const float*)wp;
        int vf = (int)f;
        if (vf >= 1 && vf <= 4096) v = vf; else v = 256;
    }
    g_win = v;
}

// ---- split fp32 -> bf16 hi + lo --------------------------------------------
__global__ __launch_bounds__(256) void split_kernel(
    const float* __restrict__ src, __nv_bfloat16* __restrict__ hi,
    __nv_bfloat16* __restrict__ lo, int n4)
{
    int i = blockIdx.x * 256 + threadIdx.x;
    if (i >= n4) return;
    float4 v = *(const float4*)(src + (size_t)i * 4);
    __nv_bfloat16 h0 = __float2bfloat16(v.x);
    __nv_bfloat16 h1 = __float2bfloat16(v.y);
    __nv_bfloat16 h2 = __float2bfloat16(v.z);
    __nv_bfloat16 h3 = __float2bfloat16(v.w);
    __nv_bfloat16 l0 = __float2bfloat16(v.x - __bfloat162float(h0));
    __nv_bfloat16 l1 = __float2bfloat16(v.y - __bfloat162float(h1));
    __nv_bfloat16 l2 = __float2bfloat16(v.z - __bfloat162float(h2));
    __nv_bfloat16 l3 = __float2bfloat16(v.w - __bfloat162float(h3));
    __nv_bfloat162* hp = (__nv_bfloat162*)(hi + (size_t)i * 4);
    __nv_bfloat162* lp = (__nv_bfloat162*)(lo + (size_t)i * 4);
    hp[0] = __halves2bfloat162(h0, h1); hp[1] = __halves2bfloat162(h2, h3);
    lp[0] = __halves2bfloat162(l0, l1); lp[1] = __halves2bfloat162(l2, l3);
}

// ---- bf16 split tensor-core GEMM + bias, 2-stage cp.async pipeline ---------
// Tile 128x128, BK=32, 256 thr (8 warps, 4m x 2n), warp tile 32x64.
// smem stage (halves): AH[128][40] AL[128][40] BH[32][136] BL[32][136]
#define OFF_AH 0
#define OFF_AL 5120
#define OFF_BH 10240
#define OFF_BL 14592
#define STAGE  18944

__global__ __launch_bounds__(256) void gemm_bf16_tc(
    const __nv_bfloat16* __restrict__ Ahg, const __nv_bfloat16* __restrict__ Alg,
    const __nv_bfloat16* __restrict__ Bhg, const __nv_bfloat16* __restrict__ Blg,
    const float* __restrict__ bias, float* __restrict__ C,
    int M, int N, int K)
{
    extern __shared__ __nv_bfloat16 smb[];
    const int tid  = threadIdx.x;
    const int bm   = blockIdx.y * 128, bn = blockIdx.x * 128;
    const int warp = tid >> 5, lane = tid & 31;
    const int wm   = (warp >> 1) * 32;
    const int wn   = (warp & 1) * 64;

    float acc[2][8][4];
#pragma unroll
    for (int i = 0; i < 2; i++)
#pragma unroll
        for (int j = 0; j < 8; j++)
#pragma unroll
            for (int r = 0; r < 4; r++) acc[i][j][r] = 0.f;

    // per-thread cp.async coords
    const int a_r = tid >> 1, a_c = (tid & 1) << 4;    // A: 128r x 32h
    const int b_r = tid >> 4, b_c = (tid & 15) << 3;   // B: 32r x 128h

    auto ld_stage = [&](int buf, int k0) {
        __nv_bfloat16* st = smb + buf * STAGE;
        {
            const __nv_bfloat16* sa = Ahg + (size_t)(bm + a_r) * K + k0 + a_c;
            const __nv_bfloat16* sl = Alg + (size_t)(bm + a_r) * K + k0 + a_c;
            uint32_t dh = smem_u32(st + OFF_AH + a_r * 40 + a_c);
            uint32_t dl = smem_u32(st + OFF_AL + a_r * 40 + a_c);
            CP16(dh, sa); CP16(dh + 16, sa + 8);
            CP16(dl, sl); CP16(dl + 16, sl + 8);
        }
        {
            const __nv_bfloat16* sb0 = Bhg + (size_t)(k0 + b_r) * N + bn + b_c;
            const __nv_bfloat16* sb1 = Bhg + (size_t)(k0 + b_r + 16) * N + bn + b_c;
            const __nv_bfloat16* sl0 = Blg + (size_t)(k0 + b_r) * N + bn + b_c;
            const __nv_bfloat16* sl1 = Blg + (size_t)(k0 + b_r + 16) * N + bn + b_c;
            CP16(smem_u32(st + OFF_BH + b_r * 136 + b_c), sb0);
            CP16(smem_u32(st + OFF_BH + (b_r + 16) * 136 + b_c), sb1);
            CP16(smem_u32(st + OFF_BL + b_r * 136 + b_c), sl0);
            CP16(smem_u32(st + OFF_BL + (b_r + 16) * 136 + b_c), sl1);
        }
    };

    ld_stage(0, 0);
    CP_COMMIT();

    const int a_row = lane & 15, a_k = (lane >> 4) << 3;
    const int b_row = lane & 15, b_n = (lane >> 4) << 3;

    int buf = 0;
    for (int k0 = 0; k0 < K; k0 += 32) {
        const bool nxt = (k0 + 32) < K;
        if (nxt) {
            ld_stage(buf ^ 1, k0 + 32);
            CP_COMMIT();
            CP_WAIT1();
        } else {
            CP_WAIT0();
        }
        __syncthreads();

        __nv_bfloat16* st = smb + buf * STAGE;
#pragma unroll
        for (int kf = 0; kf < 2; kf++) {
            uint32_t ah[2][4], al[2][4];
#pragma unroll
            for (int fm = 0; fm < 2; fm++) {
                LDSM4(ah[fm], smem_u32(st + OFF_AH + (wm + fm * 16 + a_row) * 40 + kf * 16 + a_k));
                LDSM4(al[fm], smem_u32(st + OFF_AL + (wm + fm * 16 + a_row) * 40 + kf * 16 + a_k));
            }
#pragma unroll
            for (int jn = 0; jn < 4; jn++) {
                uint32_t bh4[4], bl4[4];
                LDSM4T(bh4, smem_u32(st + OFF_BH + (kf * 16 + b_row) * 136 + wn + jn * 16 + b_n));
                LDSM4T(bl4, smem_u32(st + OFF_BL + (kf * 16 + b_row) * 136 + wn + jn * 16 + b_n));
                // pass-major: 4 independent accumulators between same-acc MMAs
#pragma unroll
                for (int fm = 0; fm < 2; fm++)
#pragma unroll
                    for (int hf = 0; hf < 2; hf++)
                        MMA16816(acc[fm][jn * 2 + hf], ah[fm], bh4[hf * 2], bh4[hf * 2 + 1]);
#pragma unroll
                for (int fm = 0; fm < 2; fm++)
#pragma unroll
                    for (int hf = 0; hf < 2; hf++)
                        MMA16816(acc[fm][jn * 2 + hf], al[fm], bh4[hf * 2], bh4[hf * 2 + 1]);
#pragma unroll
                for (int fm = 0; fm < 2; fm++)
#pragma unroll
                    for (int hf = 0; hf < 2; hf++)
                        MMA16816(acc[fm][jn * 2 + hf], ah[fm], bl4[hf * 2], bl4[hf * 2 + 1]);
            }
        }
        __syncthreads();
        buf ^= 1;
    }

    const int g = lane >> 2, tq = lane & 3;
#pragma unroll
    for (int fm = 0; fm < 2; fm++) {
#pragma unroll
        for (int nf = 0; nf < 8; nf++) {
            int col = bn + wn + nf * 8 + tq * 2;
            float2 bv = *(const float2*)(bias + col);
            int row0 = bm + wm + fm * 16 + g;
            float2 o0 = make_float2(acc[fm][nf][0] + bv.x, acc[fm][nf][1] + bv.y);
            float2 o1 = make_float2(acc[fm][nf][2] + bv.x, acc[fm][nf][3] + bv.y);
            *(float2*)(C + (size_t)row0 * N + col) = o0;
            *(float2*)(C + (size_t)(row0 + 8) * N + col) = o1;
        }
    }
}

// ---- kUr/kUn ---------------------------------------------------------------
__global__ __launch_bounds__(256) void ku_kernel(
    const float* __restrict__ Ur, const float* __restrict__ Un)
{
    __shared__ float ks[64][64];
    __shared__ float ur[64][64];
    __shared__ float un[64][64];
    const int t64 = blockIdx.x, bh = blockIdx.y;
    const int b = bh / 12, h = bh - b * 12;
    const int tid = threadIdx.x;
#pragma unroll
    for (int i = 0; i < 4; i++) {
        int s = i * 256 + tid;
        ((float4*)ur)[s] = ((const float4*)Ur)[s];
        ((float4*)un)[s] = ((const float4*)Un)[s];
    }
    const float* kb = g_qkv + ((size_t)(b * 2048 + t64 * 64)) * 2304 + 768 + h * 64;
#pragma unroll
    for (int q = 0; q < 4; q++) {
        int s = q * 256 + tid;
        int r = s >> 4, d0 = (s & 15) << 2;
        *(float4*)&ks[r][d0] = *(const float4*)(kb + (size_t)r * 2304 + d0);
    }
    __syncthreads();
    const int tx = tid & 15, ty = tid >> 4;
    ull ar[4][2], an[4][2];
#pragma unroll
    for (int i = 0; i < 4; i++)
#pragma unroll
        for (int j = 0; j < 2; j++) { ar[i][j] = 0ull; an[i][j] = 0ull; }

    for (int i0 = 0; i0 < 64; i0 += 4) {
        float krr[4][4];
#pragma unroll
        for (int rr = 0; rr < 4; rr++)
            *(float4*)&krr[rr][0] = *(const float4*)&ks[ty * 4 + rr][i0];
#pragma unroll
        for (int q = 0; q < 4; q++) {
            const ull* uR2 = (const ull*)&ur[i0 + q][tx * 4];
            const ull* uN2 = (const ull*)&un[i0 + q][tx * 4];
            ull uR0 = uR2[0], uR1 = uR2[1], uN0 = uN2[0], uN1 = uN2[1];
#pragma unroll
            for (int rr = 0; rr < 4; rr++) {
                ull kd = pk2(krr[rr][q], krr[rr][q]);
                ar[rr][0] = ffma2(kd, uR0, ar[rr][0]);
                ar[rr][1] = ffma2(kd, uR1, ar[rr][1]);
                an[rr][0] = ffma2(kd, uN0, an[rr][0]);
                an[rr][1] = ffma2(kd, uN1, an[rr][1]);
            }
        }
    }
    float* outR = g_kur + ((size_t)bh * 2048 + t64 * 64) * 64;
    float* outN = g_kun + ((size_t)bh * 2048 + t64 * 64) * 64;
#pragma unroll
    for (int rr = 0; rr < 4; rr++) {
        float2 r0 = up2(ar[rr][0]), r1 = up2(ar[rr][1]);
        float2 n0 = up2(an[rr][0]), n1 = up2(an[rr][1]);
        float4 oR = make_float4(r0.x, r0.y, r1.x, r1.y);
        float4 oN = make_float4(n0.x, n0.y, n1.x, n1.y);
        *(float4*)&outR[(size_t)(ty * 4 + rr) * 64 + tx * 4] = oR;
        *(float4*)&outN[(size_t)(ty * 4 + rr) * 64 + tx * 4] = oN;
    }
}

// ---- windowed flash attention ----------------------------------------------
__global__ __launch_bounds__(256) void attn_kernel()
{
    extern __shared__ float sm[];
    float* qs = sm;
    float* ks = qs + 64 * 68;
    float* vs = ks + 64 * 68;
    float* ps = vs + 64 * 68;
    const int qt = blockIdx.x, bh = blockIdx.y;
    const int b = bh / 12, h = bh - b * 12;
    const int tid = threadIdx.x;
    const int tx = tid & 15, ty = tid >> 4;
    const int win = g_win;

    const float* qbase = g_qkv + ((size_t)(b * 2048 + qt * 64)) * 2304 + h * 64;
#pragma unroll
    for (int q = 0; q < 4; q++) {
        int s = q * 256 + tid;
        int r = s >> 4, d0 = (s & 15) << 2;
        float4 v = *(const float4*)(qbase + (size_t)r * 2304 + d0);
        qs[(d0 + 0) * 68 + r] = v.x; qs[(d0 + 1) * 68 + r] = v.y;
        qs[(d0 + 2) * 68 + r] = v.z; qs[(d0 + 3) * 68 + r] = v.w;
    }
    ull opk[4][2];
    float m[4], l[4];
#pragma unroll
    for (int i = 0; i < 4; i++) {
        m[i] = -1e30f; l[i] = 0.f;
        opk[i][0] = 0ull; opk[i][1] = 0ull;
    }
    int ktmax = (qt * 64 + 63 + win - 1) >> 6;
    if (ktmax > 31) ktmax = 31;

    for (int kt = qt; kt <= ktmax; kt++) {
        __syncthreads();
        const float* kb = g_qkv + ((size_t)(b * 2048 + kt * 64)) * 2304 + 768 + h * 64;
        const float* vb = kb + 768;
#pragma unroll
        for (int q = 0; q < 4; q++) {
            int s = q * 256 + tid;
            int r = s >> 4, d0 = (s & 15) << 2;
            float4 kv = *(const float4*)(kb + (size_t)r * 2304 + d0);
            ks[(d0 + 0) * 68 + r] = kv.x; ks[(d0 + 1) * 68 + r] = kv.y;
            ks[(d0 + 2) * 68 + r] = kv.z; ks[(d0 + 3) * 68 + r] = kv.w;
            *(float4*)&vs[r * 68 + d0] = *(const float4*)(vb + (size_t)r * 2304 + d0);
        }
        __syncthreads();

        ull sp[4][2];
#pragma unroll
        for (int i = 0; i < 4; i++) { sp[i][0] = 0ull; sp[i][1] = 0ull; }
#pragma unroll 8
        for (int d = 0; d < 64; d++) {
            float4 qv = *(float4*)&qs[d * 68 + ty * 4];
            const ull* kp = (const ull*)&ks[d * 68 + tx * 4];
            ull k0 = kp[0], k1 = kp[1];
            ull q0 = pk2(qv.x, qv.x), q1 = pk2(qv.y, qv.y);
            ull q2 = pk2(qv.z, qv.z), q3 = pk2(qv.w, qv.w);
            sp[0][0] = ffma2(q0, k0, sp[0][0]); sp[0][1] = ffma2(q0, k1, sp[0][1]);
            sp[1][0] = ffma2(q1, k0, sp[1][0]); sp[1][1] = ffma2(q1, k1, sp[1][1]);
            sp[2][0] = ffma2(q2, k0, sp[2][0]); sp[2][1] = ffma2(q2, k1, sp[2][1]);
            sp[3][0] = ffma2(q3, k0, sp[3][0]); sp[3][1] = ffma2(q3, k1, sp[3][1]);
        }
        float s4[4][4];
#pragma unroll
        for (int i = 0; i < 4; i++) {
            float2 a = up2(sp[i][0]), bb = up2(sp[i][1]);
            s4[i][0] = a.x; s4[i][1] = a.y; s4[i][2] = bb.x; s4[i][3] = bb.y;
        }
#pragma unroll
        for (int rr = 0; rr < 4; rr++) {
            int iG = qt * 64 + ty * 4 + rr;
#pragma unroll
            for (int cc = 0; cc < 4; cc++) {
                int jG = kt * 64 + tx * 4 + cc;
                bool ok = (jG >= iG) && (jG - iG < win);
                s4[rr][cc] = ok ? s4[rr][cc] * 0.125f : -1e30f;
            }
        }
#pragma unroll
        for (int rr = 0; rr < 4; rr++) {
            float mx = fmaxf(fmaxf(s4[rr][0], s4[rr][1]), fmaxf(s4[rr][2], s4[rr][3]));
            mx = fmaxf(mx, __shfl_xor_sync(0xffffffffu, mx, 1));
            mx = fmaxf(mx, __shfl_xor_sync(0xffffffffu, mx, 2));
            mx = fmaxf(mx, __shfl_xor_sync(0xffffffffu, mx, 4));
            mx = fmaxf(mx, __shfl_xor_sync(0xffffffffu, mx, 8));
            float mnew = fmaxf(m[rr], mx);
            float corr = __expf(m[rr] - mnew);
            float rs = 0.f;
#pragma unroll
            for (int cc = 0; cc < 4; cc++) {
                s4[rr][cc] = __expf(s4[rr][cc] - mnew);
                rs += s4[rr][cc];
            }
            rs += __shfl_xor_sync(0xffffffffu, rs, 1);
            rs += __shfl_xor_sync(0xffffffffu, rs, 2);
            rs += __shfl_xor_sync(0xffffffffu, rs, 4);
            rs += __shfl_xor_sync(0xffffffffu, rs, 8);
            l[rr] = l[rr] * corr + rs;
            m[rr] = mnew;
            ull cd = pk2(corr, corr);
            opk[rr][0] = mul2(opk[rr][0], cd);
            opk[rr][1] = mul2(opk[rr][1], cd);
        }
#pragma unroll
        for (int cc = 0; cc < 4; cc++) {
            float4 pv = make_float4(s4[0][cc], s4[1][cc], s4[2][cc], s4[3][cc]);
            *(float4*)&ps[(tx * 4 + cc) * 68 + ty * 4] = pv;
        }
        __syncthreads();
#pragma unroll 8
        for (int j = 0; j < 64; j++) {
            float4 pv = *(float4*)&ps[j * 68 + ty * 4];
            const ull* vp = (const ull*)&vs[j * 68 + tx * 4];
            ull v0 = vp[0], v1 = vp[1];
            ull p0 = pk2(pv.x, pv.x), p1 = pk2(pv.y, pv.y);
            ull p2 = pk2(pv.z, pv.z), p3 = pk2(pv.w, pv.w);
            opk[0][0] = ffma2(p0, v0, opk[0][0]); opk[0][1] = ffma2(p0, v1, opk[0][1]);
            opk[1][0] = ffma2(p1, v0, opk[1][0]); opk[1][1] = ffma2(p1, v1, opk[1][1]);
            opk[2][0] = ffma2(p2, v0, opk[2][0]); opk[2][1] = ffma2(p2, v1, opk[2][1]);
            opk[3][0] = ffma2(p3, v0, opk[3][0]); opk[3][1] = ffma2(p3, v1, opk[3][1]);
        }
    }
    float* ob = g_local + ((size_t)bh * 2048 + qt * 64) * 64;
#pragma unroll
    for (int rr = 0; rr < 4; rr++) {
        float inv = 1.f / l[rr];
        float2 a = up2(opk[rr][0]), bb = up2(opk[rr][1]);
        float4 ov = make_float4(a.x * inv, a.y * inv, bb.x * inv, bb.y * inv);
        *(float4*)&ob[(size_t)(ty * 4 + rr) * 64 + tx * 4] = ov;
    }
}

// ---- GRU scan ---------------------------------------------------------------
__global__ __launch_bounds__(256, 1) void gru_kernel(
    const float* __restrict__ Wr, const float* __restrict__ Wz,
    const float* __restrict__ Wn)
{
    const int bh = blockIdx.x;
    const int b = bh / 12, h = bh - b * 12;
    const int tid = threadIdx.x;
    const int j = tid >> 2, c = tid & 3;
    __shared__ float h_sh[64];
    __shared__ float rh_sh[64];

    ull wrp[8], wzp[8], wnp[8];
#pragma unroll
    for (int q = 0; q < 8; q++) {
        int i = c * 16 + q * 2;
        wrp[q] = pk2(Wr[i * 64 + j], Wr[(i + 1) * 64 + j]);
        wzp[q] = pk2(Wz[i * 64 + j], Wz[(i + 1) * 64 + j]);
        wnp[q] = pk2(Wn[i * 64 + j], Wn[(i + 1) * 64 + j]);
    }
    if (tid < 64) h_sh[tid] = 0.f;
    __syncthreads();

    const float* kbase = g_qkv + ((size_t)b * 2048) * 2304 + 768 + h * 64;
    const float* vbase = kbase + 768;
    const float* kurb = g_kur + (size_t)bh * 2048 * 64;
    const float* kunb = g_kun + (size_t)bh * 2048 * 64;
    float* rout = g_rnn + (size_t)bh * 2048 * 64;

    float ktc = kbase[j], vtc = vbase[j], kurc = kurb[j], kunc = kunb[j];

    for (int t = 0; t < 2048; t++) {
        float ktn = 0.f, vtn = 0.f, kurn = 0.f, kunn = 0.f;
        if (t + 1 < 2048) {
            ktn  = kbase[(size_t)(t + 1) * 2304 + j];
            vtn  = vbase[(size_t)(t + 1) * 2304 + j];
            kurn = kurb[(size_t)(t + 1) * 64 + j];
            kunn = kunb[(size_t)(t + 1) * 64 + j];
        }
        ull aR = 0ull, aZ = 0ull;
        const ull* h2 = (const ull*)&h_sh[c * 16];
#pragma unroll
        for (int q = 0; q < 8; q++) {
            ull hp = h2[q];
            aR = ffma2(hp, wrp[q], aR);
            aZ = ffma2(hp, wzp[q], aZ);
        }
        float2 fR = up2(aR), fZ = up2(aZ);
        float accR = fR.x + fR.y, accZ = fZ.x + fZ.y;
        accR += __shfl_xor_sync(0xffffffffu, accR, 1);
        accR += __shfl_xor_sync(0xffffffffu, accR, 2);
        accZ += __shfl_xor_sync(0xffffffffu, accZ, 1);
        accZ += __shfl_xor_sync(0xffffffffu, accZ, 2);
        float r = 1.f / (1.f + __expf(-(accR + kurc)));
        float z = 1.f / (1.f + __expf(-(accZ + ktc)));
        float hj = h_sh[j];
        if (c == 0) rh_sh[j] = r * hj;
        __syncthreads();

        ull aN = 0ull;
        const ull* rh2 = (const ull*)&rh_sh[c * 16];
#pragma unroll
        for (int q = 0; q < 8; q++)
            aN = ffma2(rh2[q], wnp[q], aN);
        float2 fN = up2(aN);
        float accN = fN.x + fN.y;
        accN += __shfl_xor_sync(0xffffffffu, accN, 1);
        accN += __shfl_xor_sync(0xffffffffu, accN, 2);
        float n = tanhf(accN + kunc);
        float hnew = (1.f - z) * hj + z * (n * vtc);
        if (c == 0) {
            h_sh[j] = hnew;
            rout[(size_t)t * 64 + j] = hnew;
        }
        __syncthreads();

        ktc = ktn; vtc = vtn; kurc = kurn; kunc = kunn;
    }
}

// ---- gate -------------------------------------------------------------------
__global__ __launch_bounds__(256) void gate_kernel(
    const float* __restrict__ x, const float* __restrict__ gw,
    const float* __restrict__ gb)
{
    int gid = blockIdx.x * 256 + threadIdx.x;
    if (gid >= 4 * 2048 * 12) return;
    int h = gid % 12;
    int bt = gid / 12;
    const float* xr = x + (size_t)bt * 768;
    float acc = gb[h];
#pragma unroll 4
    for (int i = 0; i < 768; i++)
        acc = fmaf(__ldg(xr + i), __ldg(gw + (size_t)i * 12 + h), acc);
    g_alpha[gid] = 1.f / (1.f + __expf(-acc));
}

// ---- combine ----------------------------------------------------------------
__global__ __launch_bounds__(256) void combine_kernel()
{
    int gid = blockIdx.x * 256 + threadIdx.x;
    if (gid >= 4 * 2048 * 192) return;
    int c4 = gid % 192;
    int bt = gid / 192;
    int h = c4 >> 4, d4 = c4 & 15;
    int b = bt >> 11, t = bt & 2047;
    float a = g_alpha[bt * 12 + h];
    size_t idx = ((size_t)(b * 12 + h) * 2048 + t) * 64 + d4 * 4;
    float4 lo = *(const float4*)(g_local + idx);
    float4 rn = *(const float4*)(g_rnn + idx);
    float4 o;
    o.x = a * lo.x + (1.f - a) * rn.x;
    o.y = a * lo.y + (1.f - a) * rn.y;
    o.z = a * lo.z + (1.f - a) * rn.z;
    o.w = a * lo.w + (1.f - a) * rn.w;
    *(float4*)(g_y + (size_t)bt * 768 + c4 * 4) = o;
}

extern "C" void kernel_launch(void* const* d_in, const int* in_sizes, int n_in,
                              void* d_out, int out_size) {
    const float* x      = (const float*)d_in[0];
    const void*  winp   = d_in[1];
    const float* qkv_w  = (const float*)d_in[2];
    const float* qkv_b  = (const float*)d_in[3];
    const float* proj_w = (const float*)d_in[4];
    const float* proj_b = (const float*)d_in[5];
    const float* Wr     = (const float*)d_in[6];
    const float* Ur     = (const float*)d_in[7];
    const float* Wz     = (const float*)d_in[8];
    const float* Wn     = (const float*)d_in[9];
    const float* Un     = (const float*)d_in[10];
    const float* gate_w = (const float*)d_in[11];
    const float* gate_b = (const float*)d_in[12];
    float* out = (float*)d_out;

    float* qkv_g; cudaGetSymbolAddress((void**)&qkv_g, g_qkv);
    float* y_g;   cudaGetSymbolAddress((void**)&y_g,   g_y);
    __nv_bfloat16 *xh, *xl, *wqh, *wql, *yh, *yl, *wph, *wpl;
    cudaGetSymbolAddress((void**)&xh,  g_xh);
    cudaGetSymbolAddress((void**)&xl,  g_xl);
    cudaGetSymbolAddress((void**)&wqh, g_wqh);
    cudaGetSymbolAddress((void**)&wql, g_wql);
    cudaGetSymbolAddress((void**)&yh,  g_yh);
    cudaGetSymbolAddress((void**)&yl,  g_yl);
    cudaGetSymbolAddress((void**)&wph, g_wph);
    cudaGetSymbolAddress((void**)&wpl, g_wpl);

    cudaFuncSetAttribute(attn_kernel,
        cudaFuncAttributeMaxDynamicSharedMemorySize, 4 * 64 * 68 * 4);
    cudaFuncSetAttribute(gemm_bf16_tc,
        cudaFuncAttributeMaxDynamicSharedMemorySize, 2 * STAGE * 2 + 256);

    win_kernel<<<1, 1>>>(winp);

    // pre-split operands to bf16 hi/lo (once)
    split_kernel<<<(8192 * 768 / 4 + 255) / 256, 256>>>(x, xh, xl, 8192 * 768 / 4);
    split_kernel<<<(768 * 2304 / 4 + 255) / 256, 256>>>(qkv_w, wqh, wql, 768 * 2304 / 4);
    split_kernel<<<(768 * 768 / 4 + 255) / 256, 256>>>(proj_w, wph, wpl, 768 * 768 / 4);

    // qkv = x @ qkv_w + qkv_b
    gemm_bf16_tc<<<dim3(18, 64), 256, 2 * STAGE * 2 + 256>>>(
        xh, xl, wqh, wql, qkv_b, qkv_g, 8192, 2304, 768);

    ku_kernel<<<dim3(32, 48), 256>>>(Ur, Un);
    attn_kernel<<<dim3(32, 48), 256, 4 * 64 * 68 * 4>>>();
    gru_kernel<<<48, 256>>>(Wr, Wz, Wn);
    gate_kernel<<<384, 256>>>(x, gate_w, gate_b);
    combine_kernel<<<6144, 256>>>();

    // split y, then out = y @ proj_w + proj_b
    split_kernel<<<(8192 * 768 / 4 + 255) / 256, 256>>>(y_g, yh, yl, 8192 * 768 / 4);
    gemm_bf16_tc<<<dim3(6, 64), 256, 2 * STAGE * 2 + 256>>>(
        yh, yl, wph, wpl, proj_b, out, 8192, 768, 768);
}

// round 10
// speedup vs baseline: 1.1386x; 1.0062x over previous
#include <cuda_runtime.h>
#include <cuda_bf16.h>
#include <cstdint>

// B=4, T=2048, C=768, H=12, D=64, 3C=2304, BH=48

typedef unsigned long long ull;

__device__ float g_qkv  [4*2048*2304];   // [B,T,3C]
__device__ float g_kur  [48*2048*64];
__device__ float g_kun  [48*2048*64];
__device__ float g_local[48*2048*64];
__device__ float g_rnn  [48*2048*64];
__device__ float g_alpha[4*2048*12];
__device__ int   g_win;

// bf16 hi/lo split buffers
__device__ __nv_bfloat16 g_xh [4*2048*768];
__device__ __nv_bfloat16 g_xl [4*2048*768];
__device__ __nv_bfloat16 g_wqh[768*2304];
__device__ __nv_bfloat16 g_wql[768*2304];
__device__ __nv_bfloat16 g_yh [4*2048*768];
__device__ __nv_bfloat16 g_yl [4*2048*768];
__device__ __nv_bfloat16 g_wph[768*768];
__device__ __nv_bfloat16 g_wpl[768*768];

// ---- packed f32x2 helpers ---------------------------------------------------
__device__ __forceinline__ ull ffma2(ull a, ull b, ull c) {
    ull d;
    asm("fma.rn.f32x2 %0, %1, %2, %3;" : "=l"(d) : "l"(a), "l"(b), "l"(c));
    return d;
}
__device__ __forceinline__ ull mul2(ull a, ull b) {
    ull d;
    asm("mul.rn.f32x2 %0, %1, %2;" : "=l"(d) : "l"(a), "l"(b));
    return d;
}
__device__ __forceinline__ ull pk2(float x, float y) {
    ull r;
    asm("mov.b64 %0, {%1, %2};" : "=l"(r) : "f"(x), "f"(y));
    return r;
}
__device__ __forceinline__ float2 up2(ull v) {
    float2 f;
    asm("mov.b64 {%0, %1}, %2;" : "=f"(f.x), "=f"(f.y) : "l"(v));
    return f;
}

// ---- tensor-core / async primitives ----------------------------------------
#define LDSM4(r, addr) \
    asm volatile("ldmatrix.sync.aligned.m8n8.x4.shared.b16 {%0,%1,%2,%3}, [%4];" \
        : "=r"((r)[0]), "=r"((r)[1]), "=r"((r)[2]), "=r"((r)[3]) : "r"(addr))
#define LDSM4T(r, addr) \
    asm volatile("ldmatrix.sync.aligned.m8n8.x4.trans.shared.b16 {%0,%1,%2,%3}, [%4];" \
        : "=r"((r)[0]), "=r"((r)[1]), "=r"((r)[2]), "=r"((r)[3]) : "r"(addr))
#define MMA16816(d, a, b0v, b1v) \
    asm volatile("mma.sync.aligned.m16n8k16.row.col.f32.bf16.bf16.f32 " \
        "{%0,%1,%2,%3}, {%4,%5,%6,%7}, {%8,%9}, {%0,%1,%2,%3};" \
        : "+f"((d)[0]), "+f"((d)[1]), "+f"((d)[2]), "+f"((d)[3]) \
        : "r"((a)[0]), "r"((a)[1]), "r"((a)[2]), "r"((a)[3]), "r"(b0v), "r"(b1v))
#define CP16(dst, src) \
    asm volatile("cp.async.cg.shared.global [%0], [%1], 16;" :: "r"(dst), "l"(src))
#define CP_COMMIT() asm volatile("cp.async.commit_group;" ::: "memory")
#define CP_WAIT0()  asm volatile("cp.async.wait_group 0;" ::: "memory")
#define CP_WAIT1()  asm volatile("cp.async.wait_group 1;" ::: "memory")

__device__ __forceinline__ uint32_t smem_u32(const void* p) {
    return (uint32_t)__cvta_generic_to_shared(p);
}

// ---- window scalar normalization -------------------------------------------
__global__ void win_kernel(const void* wp) {
    int v = *(const int*)wp;
    if (v < 1 || v > 4096) {
        float f = *(const float*)wp;
        int vf = (int)f;
        if (vf >= 1 && vf <= 4096) v = vf; else v = 256;
    }
    g_win = v;
}

// ---- split fp32 -> bf16 hi + lo --------------------------------------------
__global__ __launch_bounds__(256) void split_kernel(
    const float* __restrict__ src, __nv_bfloat16* __restrict__ hi,
    __nv_bfloat16* __restrict__ lo, int n4)
{
    int i = blockIdx.x * 256 + threadIdx.x;
    if (i >= n4) return;
    float4 v = *(const float4*)(src + (size_t)i * 4);
    __nv_bfloat16 h0 = __float2bfloat16(v.x);
    __nv_bfloat16 h1 = __float2bfloat16(v.y);
    __nv_bfloat16 h2 = __float2bfloat16(v.z);
    __nv_bfloat16 h3 = __float2bfloat16(v.w);
    __nv_bfloat16 l0 = __float2bfloat16(v.x - __bfloat162float(h0));
    __nv_bfloat16 l1 = __float2bfloat16(v.y - __bfloat162float(h1));
    __nv_bfloat16 l2 = __float2bfloat16(v.z - __bfloat162float(h2));
    __nv_bfloat16 l3 = __float2bfloat16(v.w - __bfloat162float(h3));
    __nv_bfloat162* hp = (__nv_bfloat162*)(hi + (size_t)i * 4);
    __nv_bfloat162* lp = (__nv_bfloat162*)(lo + (size_t)i * 4);
    hp[0] = __halves2bfloat162(h0, h1); hp[1] = __halves2bfloat162(h2, h3);
    lp[0] = __halves2bfloat162(l0, l1); lp[1] = __halves2bfloat162(l2, l3);
}

// ---- bf16 split tensor-core GEMM + bias, 2-stage cp.async pipeline ---------
#define OFF_AH 0
#define OFF_AL 5120
#define OFF_BH 10240
#define OFF_BL 14592
#define STAGE  18944

__global__ __launch_bounds__(256) void gemm_bf16_tc(
    const __nv_bfloat16* __restrict__ Ahg, const __nv_bfloat16* __restrict__ Alg,
    const __nv_bfloat16* __restrict__ Bhg, const __nv_bfloat16* __restrict__ Blg,
    const float* __restrict__ bias, float* __restrict__ C,
    int M, int N, int K)
{
    extern __shared__ __nv_bfloat16 smb[];
    const int tid  = threadIdx.x;
    const int bm   = blockIdx.y * 128, bn = blockIdx.x * 128;
    const int warp = tid >> 5, lane = tid & 31;
    const int wm   = (warp >> 1) * 32;
    const int wn   = (warp & 1) * 64;

    float acc[2][8][4];
#pragma unroll
    for (int i = 0; i < 2; i++)
#pragma unroll
        for (int j = 0; j < 8; j++)
#pragma unroll
            for (int r = 0; r < 4; r++) acc[i][j][r] = 0.f;

    const int a_r = tid >> 1, a_c = (tid & 1) << 4;
    const int b_r = tid >> 4, b_c = (tid & 15) << 3;

    auto ld_stage = [&](int buf, int k0) {
        __nv_bfloat16* st = smb + buf * STAGE;
        {
            const __nv_bfloat16* sa = Ahg + (size_t)(bm + a_r) * K + k0 + a_c;
            const __nv_bfloat16* sl = Alg + (size_t)(bm + a_r) * K + k0 + a_c;
            uint32_t dh = smem_u32(st + OFF_AH + a_r * 40 + a_c);
            uint32_t dl = smem_u32(st + OFF_AL + a_r * 40 + a_c);
            CP16(dh, sa); CP16(dh + 16, sa + 8);
            CP16(dl, sl); CP16(dl + 16, sl + 8);
        }
        {
            const __nv_bfloat16* sb0 = Bhg + (size_t)(k0 + b_r) * N + bn + b_c;
            const __nv_bfloat16* sb1 = Bhg + (size_t)(k0 + b_r + 16) * N + bn + b_c;
            const __nv_bfloat16* sl0 = Blg + (size_t)(k0 + b_r) * N + bn + b_c;
            const __nv_bfloat16* sl1 = Blg + (size_t)(k0 + b_r + 16) * N + bn + b_c;
            CP16(smem_u32(st + OFF_BH + b_r * 136 + b_c), sb0);
            CP16(smem_u32(st + OFF_BH + (b_r + 16) * 136 + b_c), sb1);
            CP16(smem_u32(st + OFF_BL + b_r * 136 + b_c), sl0);
            CP16(smem_u32(st + OFF_BL + (b_r + 16) * 136 + b_c), sl1);
        }
    };

    ld_stage(0, 0);
    CP_COMMIT();

    const int a_row = lane & 15, a_k = (lane >> 4) << 3;
    const int b_row = lane & 15, b_n = (lane >> 4) << 3;

    int buf = 0;
    for (int k0 = 0; k0 < K; k0 += 32) {
        const bool nxt = (k0 + 32) < K;
        if (nxt) {
            ld_stage(buf ^ 1, k0 + 32);
            CP_COMMIT();
            CP_WAIT1();
        } else {
            CP_WAIT0();
        }
        __syncthreads();

        __nv_bfloat16* st = smb + buf * STAGE;
#pragma unroll
        for (int kf = 0; kf < 2; kf++) {
            uint32_t ah[2][4], al[2][4];
#pragma unroll
            for (int fm = 0; fm < 2; fm++) {
                LDSM4(ah[fm], smem_u32(st + OFF_AH + (wm + fm * 16 + a_row) * 40 + kf * 16 + a_k));
                LDSM4(al[fm], smem_u32(st + OFF_AL + (wm + fm * 16 + a_row) * 40 + kf * 16 + a_k));
            }
#pragma unroll
            for (int jn = 0; jn < 4; jn++) {
                uint32_t bh4[4], bl4[4];
                LDSM4T(bh4, smem_u32(st + OFF_BH + (kf * 16 + b_row) * 136 + wn + jn * 16 + b_n));
                LDSM4T(bl4, smem_u32(st + OFF_BL + (kf * 16 + b_row) * 136 + wn + jn * 16 + b_n));
#pragma unroll
                for (int fm = 0; fm < 2; fm++)
#pragma unroll
                    for (int hf = 0; hf < 2; hf++)
                        MMA16816(acc[fm][jn * 2 + hf], ah[fm], bh4[hf * 2], bh4[hf * 2 + 1]);
#pragma unroll
                for (int fm = 0; fm < 2; fm++)
#pragma unroll
                    for (int hf = 0; hf < 2; hf++)
                        MMA16816(acc[fm][jn * 2 + hf], al[fm], bh4[hf * 2], bh4[hf * 2 + 1]);
#pragma unroll
                for (int fm = 0; fm < 2; fm++)
#pragma unroll
                    for (int hf = 0; hf < 2; hf++)
                        MMA16816(acc[fm][jn * 2 + hf], ah[fm], bl4[hf * 2], bl4[hf * 2 + 1]);
            }
        }
        __syncthreads();
        buf ^= 1;
    }

    const int g = lane >> 2, tq = lane & 3;
#pragma unroll
    for (int fm = 0; fm < 2; fm++) {
#pragma unroll
        for (int nf = 0; nf < 8; nf++) {
            int col = bn + wn + nf * 8 + tq * 2;
            float2 bv = *(const float2*)(bias + col);
            int row0 = bm + wm + fm * 16 + g;
            float2 o0 = make_float2(acc[fm][nf][0] + bv.x, acc[fm][nf][1] + bv.y);
            float2 o1 = make_float2(acc[fm][nf][2] + bv.x, acc[fm][nf][3] + bv.y);
            *(float2*)(C + (size_t)row0 * N + col) = o0;
            *(float2*)(C + (size_t)(row0 + 8) * N + col) = o1;
        }
    }
}

// ---- kUr/kUn ---------------------------------------------------------------
__global__ __launch_bounds__(256) void ku_kernel(
    const float* __restrict__ Ur, const float* __restrict__ Un)
{
    __shared__ float ks[64][64];
    __shared__ float ur[64][64];
    __shared__ float un[64][64];
    const int t64 = blockIdx.x, bh = blockIdx.y;
    const int b = bh / 12, h = bh - b * 12;
    const int tid = threadIdx.x;
#pragma unroll
    for (int i = 0; i < 4; i++) {
        int s = i * 256 + tid;
        ((float4*)ur)[s] = ((const float4*)Ur)[s];
        ((float4*)un)[s] = ((const float4*)Un)[s];
    }
    const float* kb = g_qkv + ((size_t)(b * 2048 + t64 * 64)) * 2304 + 768 + h * 64;
#pragma unroll
    for (int q = 0; q < 4; q++) {
        int s = q * 256 + tid;
        int r = s >> 4, d0 = (s & 15) << 2;
        *(float4*)&ks[r][d0] = *(const float4*)(kb + (size_t)r * 2304 + d0);
    }
    __syncthreads();
    const int tx = tid & 15, ty = tid >> 4;
    ull ar[4][2], an[4][2];
#pragma unroll
    for (int i = 0; i < 4; i++)
#pragma unroll
        for (int j = 0; j < 2; j++) { ar[i][j] = 0ull; an[i][j] = 0ull; }

    for (int i0 = 0; i0 < 64; i0 += 4) {
        float krr[4][4];
#pragma unroll
        for (int rr = 0; rr < 4; rr++)
            *(float4*)&krr[rr][0] = *(const float4*)&ks[ty * 4 + rr][i0];
#pragma unroll
        for (int q = 0; q < 4; q++) {
            const ull* uR2 = (const ull*)&ur[i0 + q][tx * 4];
            const ull* uN2 = (const ull*)&un[i0 + q][tx * 4];
            ull uR0 = uR2[0], uR1 = uR2[1], uN0 = uN2[0], uN1 = uN2[1];
#pragma unroll
            for (int rr = 0; rr < 4; rr++) {
                ull kd = pk2(krr[rr][q], krr[rr][q]);
                ar[rr][0] = ffma2(kd, uR0, ar[rr][0]);
                ar[rr][1] = ffma2(kd, uR1, ar[rr][1]);
                an[rr][0] = ffma2(kd, uN0, an[rr][0]);
                an[rr][1] = ffma2(kd, uN1, an[rr][1]);
            }
        }
    }
    float* outR = g_kur + ((size_t)bh * 2048 + t64 * 64) * 64;
    float* outN = g_kun + ((size_t)bh * 2048 + t64 * 64) * 64;
#pragma unroll
    for (int rr = 0; rr < 4; rr++) {
        float2 r0 = up2(ar[rr][0]), r1 = up2(ar[rr][1]);
        float2 n0 = up2(an[rr][0]), n1 = up2(an[rr][1]);
        float4 oR = make_float4(r0.x, r0.y, r1.x, r1.y);
        float4 oN = make_float4(n0.x, n0.y, n1.x, n1.y);
        *(float4*)&outR[(size_t)(ty * 4 + rr) * 64 + tx * 4] = oR;
        *(float4*)&outN[(size_t)(ty * 4 + rr) * 64 + tx * 4] = oN;
    }
}

// ---- windowed flash attention ----------------------------------------------
__global__ __launch_bounds__(256) void attn_kernel()
{
    extern __shared__ float sm[];
    float* qs = sm;
    float* ks = qs + 64 * 68;
    float* vs = ks + 64 * 68;
    float* ps = vs + 64 * 68;
    const int qt = blockIdx.x, bh = blockIdx.y;
    const int b = bh / 12, h = bh - b * 12;
    const int tid = threadIdx.x;
    const int tx = tid & 15, ty = tid >> 4;
    const int win = g_win;

    const float* qbase = g_qkv + ((size_t)(b * 2048 + qt * 64)) * 2304 + h * 64;
#pragma unroll
    for (int q = 0; q < 4; q++) {
        int s = q * 256 + tid;
        int r = s >> 4, d0 = (s & 15) << 2;
        float4 v = *(const float4*)(qbase + (size_t)r * 2304 + d0);
        qs[(d0 + 0) * 68 + r] = v.x; qs[(d0 + 1) * 68 + r] = v.y;
        qs[(d0 + 2) * 68 + r] = v.z; qs[(d0 + 3) * 68 + r] = v.w;
    }
    ull opk[4][2];
    float m[4], l[4];
#pragma unroll
    for (int i = 0; i < 4; i++) {
        m[i] = -1e30f; l[i] = 0.f;
        opk[i][0] = 0ull; opk[i][1] = 0ull;
    }
    int ktmax = (qt * 64 + 63 + win - 1) >> 6;
    if (ktmax > 31) ktmax = 31;

    for (int kt = qt; kt <= ktmax; kt++) {
        __syncthreads();
        const float* kb = g_qkv + ((size_t)(b * 2048 + kt * 64)) * 2304 + 768 + h * 64;
        const float* vb = kb + 768;
#pragma unroll
        for (int q = 0; q < 4; q++) {
            int s = q * 256 + tid;
            int r = s >> 4, d0 = (s & 15) << 2;
            float4 kv = *(const float4*)(kb + (size_t)r * 2304 + d0);
            ks[(d0 + 0) * 68 + r] = kv.x; ks[(d0 + 1) * 68 + r] = kv.y;
            ks[(d0 + 2) * 68 + r] = kv.z; ks[(d0 + 3) * 68 + r] = kv.w;
            *(float4*)&vs[r * 68 + d0] = *(const float4*)(vb + (size_t)r * 2304 + d0);
        }
        __syncthreads();

        ull sp[4][2];
#pragma unroll
        for (int i = 0; i < 4; i++) { sp[i][0] = 0ull; sp[i][1] = 0ull; }
#pragma unroll 8
        for (int d = 0; d < 64; d++) {
            float4 qv = *(float4*)&qs[d * 68 + ty * 4];
            const ull* kp = (const ull*)&ks[d * 68 + tx * 4];
            ull k0 = kp[0], k1 = kp[1];
            ull q0 = pk2(qv.x, qv.x), q1 = pk2(qv.y, qv.y);
            ull q2 = pk2(qv.z, qv.z), q3 = pk2(qv.w, qv.w);
            sp[0][0] = ffma2(q0, k0, sp[0][0]); sp[0][1] = ffma2(q0, k1, sp[0][1]);
            sp[1][0] = ffma2(q1, k0, sp[1][0]); sp[1][1] = ffma2(q1, k1, sp[1][1]);
            sp[2][0] = ffma2(q2, k0, sp[2][0]); sp[2][1] = ffma2(q2, k1, sp[2][1]);
            sp[3][0] = ffma2(q3, k0, sp[3][0]); sp[3][1] = ffma2(q3, k1, sp[3][1]);
        }
        float s4[4][4];
#pragma unroll
        for (int i = 0; i < 4; i++) {
            float2 a = up2(sp[i][0]), bb = up2(sp[i][1]);
            s4[i][0] = a.x; s4[i][1] = a.y; s4[i][2] = bb.x; s4[i][3] = bb.y;
        }
#pragma unroll
        for (int rr = 0; rr < 4; rr++) {
            int iG = qt * 64 + ty * 4 + rr;
#pragma unroll
            for (int cc = 0; cc < 4; cc++) {
                int jG = kt * 64 + tx * 4 + cc;
                bool ok = (jG >= iG) && (jG - iG < win);
                s4[rr][cc] = ok ? s4[rr][cc] * 0.125f : -1e30f;
            }
        }
#pragma unroll
        for (int rr = 0; rr < 4; rr++) {
            float mx = fmaxf(fmaxf(s4[rr][0], s4[rr][1]), fmaxf(s4[rr][2], s4[rr][3]));
            mx = fmaxf(mx, __shfl_xor_sync(0xffffffffu, mx, 1));
            mx = fmaxf(mx, __shfl_xor_sync(0xffffffffu, mx, 2));
            mx = fmaxf(mx, __shfl_xor_sync(0xffffffffu, mx, 4));
            mx = fmaxf(mx, __shfl_xor_sync(0xffffffffu, mx, 8));
            float mnew = fmaxf(m[rr], mx);
            float corr = __expf(m[rr] - mnew);
            float rs = 0.f;
#pragma unroll
            for (int cc = 0; cc < 4; cc++) {
                s4[rr][cc] = __expf(s4[rr][cc] - mnew);
                rs += s4[rr][cc];
            }
            rs += __shfl_xor_sync(0xffffffffu, rs, 1);
            rs += __shfl_xor_sync(0xffffffffu, rs, 2);
            rs += __shfl_xor_sync(0xffffffffu, rs, 4);
            rs += __shfl_xor_sync(0xffffffffu, rs, 8);
            l[rr] = l[rr] * corr + rs;
            m[rr] = mnew;
            ull cd = pk2(corr, corr);
            opk[rr][0] = mul2(opk[rr][0], cd);
            opk[rr][1] = mul2(opk[rr][1], cd);
        }
#pragma unroll
        for (int cc = 0; cc < 4; cc++) {
            float4 pv = make_float4(s4[0][cc], s4[1][cc], s4[2][cc], s4[3][cc]);
            *(float4*)&ps[(tx * 4 + cc) * 68 + ty * 4] = pv;
        }
        __syncthreads();
#pragma unroll 8
        for (int j = 0; j < 64; j++) {
            float4 pv = *(float4*)&ps[j * 68 + ty * 4];
            const ull* vp = (const ull*)&vs[j * 68 + tx * 4];
            ull v0 = vp[0], v1 = vp[1];
            ull p0 = pk2(pv.x, pv.x), p1 = pk2(pv.y, pv.y);
            ull p2 = pk2(pv.z, pv.z), p3 = pk2(pv.w, pv.w);
            opk[0][0] = ffma2(p0, v0, opk[0][0]); opk[0][1] = ffma2(p0, v1, opk[0][1]);
            opk[1][0] = ffma2(p1, v0, opk[1][0]); opk[1][1] = ffma2(p1, v1, opk[1][1]);
            opk[2][0] = ffma2(p2, v0, opk[2][0]); opk[2][1] = ffma2(p2, v1, opk[2][1]);
            opk[3][0] = ffma2(p3, v0, opk[3][0]); opk[3][1] = ffma2(p3, v1, opk[3][1]);
        }
    }
    float* ob = g_local + ((size_t)bh * 2048 + qt * 64) * 64;
#pragma unroll
    for (int rr = 0; rr < 4; rr++) {
        float inv = 1.f / l[rr];
        float2 a = up2(opk[rr][0]), bb = up2(opk[rr][1]);
        float4 ov = make_float4(a.x * inv, a.y * inv, bb.x * inv, bb.y * inv);
        *(float4*)&ob[(size_t)(ty * 4 + rr) * 64 + tx * 4] = ov;
    }
}

// ---- GRU scan ---------------------------------------------------------------
__global__ __launch_bounds__(256, 1) void gru_kernel(
    const float* __restrict__ Wr, const float* __restrict__ Wz,
    const float* __restrict__ Wn)
{
    const int bh = blockIdx.x;
    const int b = bh / 12, h = bh - b * 12;
    const int tid = threadIdx.x;
    const int j = tid >> 2, c = tid & 3;
    __shared__ float h_sh[64];
    __shared__ float rh_sh[64];

    ull wrp[8], wzp[8], wnp[8];
#pragma unroll
    for (int q = 0; q < 8; q++) {
        int i = c * 16 + q * 2;
        wrp[q] = pk2(Wr[i * 64 + j], Wr[(i + 1) * 64 + j]);
        wzp[q] = pk2(Wz[i * 64 + j], Wz[(i + 1) * 64 + j]);
        wnp[q] = pk2(Wn[i * 64 + j], Wn[(i + 1) * 64 + j]);
    }
    if (tid < 64) h_sh[tid] = 0.f;
    __syncthreads();

    const float* kbase = g_qkv + ((size_t)b * 2048) * 2304 + 768 + h * 64;
    const float* vbase = kbase + 768;
    const float* kurb = g_kur + (size_t)bh * 2048 * 64;
    const float* kunb = g_kun + (size_t)bh * 2048 * 64;
    float* rout = g_rnn + (size_t)bh * 2048 * 64;

    float ktc = kbase[j], vtc = vbase[j], kurc = kurb[j], kunc = kunb[j];

    for (int t = 0; t < 2048; t++) {
        float ktn = 0.f, vtn = 0.f, kurn = 0.f, kunn = 0.f;
        if (t + 1 < 2048) {
            ktn  = kbase[(size_t)(t + 1) * 2304 + j];
            vtn  = vbase[(size_t)(t + 1) * 2304 + j];
            kurn = kurb[(size_t)(t + 1) * 64 + j];
            kunn = kunb[(size_t)(t + 1) * 64 + j];
        }
        ull aR = 0ull, aZ = 0ull;
        const ull* h2 = (const ull*)&h_sh[c * 16];
#pragma unroll
        for (int q = 0; q < 8; q++) {
            ull hp = h2[q];
            aR = ffma2(hp, wrp[q], aR);
            aZ = ffma2(hp, wzp[q], aZ);
        }
        float2 fR = up2(aR), fZ = up2(aZ);
        float accR = fR.x + fR.y, accZ = fZ.x + fZ.y;
        accR += __shfl_xor_sync(0xffffffffu, accR, 1);
        accR += __shfl_xor_sync(0xffffffffu, accR, 2);
        accZ += __shfl_xor_sync(0xffffffffu, accZ, 1);
        accZ += __shfl_xor_sync(0xffffffffu, accZ, 2);
        float r = 1.f / (1.f + __expf(-(accR + kurc)));
        float z = 1.f / (1.f + __expf(-(accZ + ktc)));
        float hj = h_sh[j];
        if (c == 0) rh_sh[j] = r * hj;
        __syncthreads();

        ull aN = 0ull;
        const ull* rh2 = (const ull*)&rh_sh[c * 16];
#pragma unroll
        for (int q = 0; q < 8; q++)
            aN = ffma2(rh2[q], wnp[q], aN);
        float2 fN = up2(aN);
        float accN = fN.x + fN.y;
        accN += __shfl_xor_sync(0xffffffffu, accN, 1);
        accN += __shfl_xor_sync(0xffffffffu, accN, 2);
        float n = tanhf(accN + kunc);
        float hnew = (1.f - z) * hj + z * (n * vtc);
        if (c == 0) {
            h_sh[j] = hnew;
            rout[(size_t)t * 64 + j] = hnew;
        }
        __syncthreads();

        ktc = ktn; vtc = vtn; kurc = kurn; kunc = kunn;
    }
}

// ---- gate -------------------------------------------------------------------
__global__ __launch_bounds__(256) void gate_kernel(
    const float* __restrict__ x, const float* __restrict__ gw,
    const float* __restrict__ gb)
{
    int gid = blockIdx.x * 256 + threadIdx.x;
    if (gid >= 4 * 2048 * 12) return;
    int h = gid % 12;
    int bt = gid / 12;
    const float* xr = x + (size_t)bt * 768;
    float acc = gb[h];
#pragma unroll 4
    for (int i = 0; i < 768; i++)
        acc = fmaf(__ldg(xr + i), __ldg(gw + (size_t)i * 12 + h), acc);
    g_alpha[gid] = 1.f / (1.f + __expf(-acc));
}

// ---- combine + fused split: y -> (yh, yl) directly --------------------------
__global__ __launch_bounds__(256) void combine_split_kernel()
{
    int gid = blockIdx.x * 256 + threadIdx.x;
    if (gid >= 4 * 2048 * 192) return;
    int c4 = gid % 192;
    int bt = gid / 192;
    int h = c4 >> 4, d4 = c4 & 15;
    int b = bt >> 11, t = bt & 2047;
    float a = g_alpha[bt * 12 + h];
    size_t idx = ((size_t)(b * 12 + h) * 2048 + t) * 64 + d4 * 4;
    float4 lo = *(const float4*)(g_local + idx);
    float4 rn = *(const float4*)(g_rnn + idx);
    float4 o;
    o.x = a * lo.x + (1.f - a) * rn.x;
    o.y = a * lo.y + (1.f - a) * rn.y;
    o.z = a * lo.z + (1.f - a) * rn.z;
    o.w = a * lo.w + (1.f - a) * rn.w;
    __nv_bfloat16 h0 = __float2bfloat16(o.x);
    __nv_bfloat16 h1 = __float2bfloat16(o.y);
    __nv_bfloat16 h2 = __float2bfloat16(o.z);
    __nv_bfloat16 h3 = __float2bfloat16(o.w);
    __nv_bfloat16 l0 = __float2bfloat16(o.x - __bfloat162float(h0));
    __nv_bfloat16 l1 = __float2bfloat16(o.y - __bfloat162float(h1));
    __nv_bfloat16 l2 = __float2bfloat16(o.z - __bfloat162float(h2));
    __nv_bfloat16 l3 = __float2bfloat16(o.w - __bfloat162float(h3));
    size_t oidx = (size_t)bt * 768 + c4 * 4;
    __nv_bfloat162* hp = (__nv_bfloat162*)(g_yh + oidx);
    __nv_bfloat162* lp = (__nv_bfloat162*)(g_yl + oidx);
    hp[0] = __halves2bfloat162(h0, h1); hp[1] = __halves2bfloat162(h2, h3);
    lp[0] = __halves2bfloat162(l0, l1); lp[1] = __halves2bfloat162(l2, l3);
}

extern "C" void kernel_launch(void* const* d_in, const int* in_sizes, int n_in,
                              void* d_out, int out_size) {
    const float* x      = (const float*)d_in[0];
    const void*  winp   = d_in[1];
    const float* qkv_w  = (const float*)d_in[2];
    const float* qkv_b  = (const float*)d_in[3];
    const float* proj_w = (const float*)d_in[4];
    const float* proj_b = (const float*)d_in[5];
    const float* Wr     = (const float*)d_in[6];
    const float* Ur     = (const float*)d_in[7];
    const float* Wz     = (const float*)d_in[8];
    const float* Wn     = (const float*)d_in[9];
    const float* Un     = (const float*)d_in[10];
    const float* gate_w = (const float*)d_in[11];
    const float* gate_b = (const float*)d_in[12];
    float* out = (float*)d_out;

    float* qkv_g; cudaGetSymbolAddress((void**)&qkv_g, g_qkv);
    __nv_bfloat16 *xh, *xl, *wqh, *wql, *yh, *yl, *wph, *wpl;
    cudaGetSymbolAddress((void**)&xh,  g_xh);
    cudaGetSymbolAddress((void**)&xl,  g_xl);
    cudaGetSymbolAddress((void**)&wqh, g_wqh);
    cudaGetSymbolAddress((void**)&wql, g_wql);
    cudaGetSymbolAddress((void**)&yh,  g_yh);
    cudaGetSymbolAddress((void**)&yl,  g_yl);
    cudaGetSymbolAddress((void**)&wph, g_wph);
    cudaGetSymbolAddress((void**)&wpl, g_wpl);

    cudaFuncSetAttribute(attn_kernel,
        cudaFuncAttributeMaxDynamicSharedMemorySize, 4 * 64 * 68 * 4);
    cudaFuncSetAttribute(gemm_bf16_tc,
        cudaFuncAttributeMaxDynamicSharedMemorySize, 2 * STAGE * 2 + 256);

    // streams/events created once, on the first (uncaptured) correctness call
    static cudaStream_t s1 = nullptr, s2 = nullptr;
    static cudaEvent_t evStart = nullptr, evQ = nullptr, evA = nullptr, evG = nullptr;
    if (s1 == nullptr) {
        cudaStreamCreateWithFlags(&s1, cudaStreamNonBlocking);
        cudaStreamCreateWithFlags(&s2, cudaStreamNonBlocking);
        cudaEventCreateWithFlags(&evStart, cudaEventDisableTiming);
        cudaEventCreateWithFlags(&evQ, cudaEventDisableTiming);
        cudaEventCreateWithFlags(&evA, cudaEventDisableTiming);
        cudaEventCreateWithFlags(&evG, cudaEventDisableTiming);
    }

    // fork s2: gate + proj_w split depend only on inputs
    cudaEventRecord(evStart, 0);
    cudaStreamWaitEvent(s2, evStart, 0);
    gate_kernel<<<384, 256, 0, s2>>>(x, gate_w, gate_b);
    split_kernel<<<(768 * 768 / 4 + 255) / 256, 256, 0, s2>>>(
        proj_w, wph, wpl, 768 * 768 / 4);
    cudaEventRecord(evG, s2);

    // main chain
    win_kernel<<<1, 1>>>(winp);
    split_kernel<<<(8192 * 768 / 4 + 255) / 256, 256>>>(x, xh, xl, 8192 * 768 / 4);
    split_kernel<<<(768 * 2304 / 4 + 255) / 256, 256>>>(qkv_w, wqh, wql, 768 * 2304 / 4);
    gemm_bf16_tc<<<dim3(18, 64), 256, 2 * STAGE * 2 + 256>>>(
        xh, xl, wqh, wql, qkv_b, qkv_g, 8192, 2304, 768);
    cudaEventRecord(evQ, 0);

    // fork s1: attention runs concurrently with ku+gru
    cudaStreamWaitEvent(s1, evQ, 0);
    attn_kernel<<<dim3(32, 48), 256, 4 * 64 * 68 * 4, s1>>>();
    cudaEventRecord(evA, s1);

    ku_kernel<<<dim3(32, 48), 256>>>(Ur, Un);
    gru_kernel<<<48, 256>>>(Wr, Wz, Wn);

    // join
    cudaStreamWaitEvent(0, evA, 0);
    cudaStreamWaitEvent(0, evG, 0);
    combine_split_kernel<<<6144, 256>>>();
    gemm_bf16_tc<<<dim3(6, 64), 256, 2 * STAGE * 2 + 256>>>(
        yh, yl, wph, wpl, proj_b, out, 8192, 768, 768);
}